// round 7
// baseline (speedup 1.0000x reference)
#include <cuda_runtime.h>
#include <cuda_fp16.h>
#include <cstdint>

#define NROWS 32768
#define DIM   768
#define NQ    4
#define NV    4096
#define DELTA 0.25f

#define GBM 128
#define GBN 128
#define KTOT 768           // hi-only screen GEMM
#define BK   64
#define NSTG (KTOT / BK)   // 12
#define NBUF 3
#define NT2  (NV / GBN)    // 32
#define MT2  (NROWS / GBM) // 256
#define SROW  72           // half elems per smem row (64 + 8 pad)
#define SROWB 144          // bytes per smem row
#define BUFSZ (128 * SROWB)            // 18432 B per matrix per buffer
#define SMEM_DYN (NBUF * 2 * BUFSZ)    // 110592 B
#define NSEG 128           // NT2 * 4 warp-col segments of 32 cols

// ---------------- scratch ---------------------------------------------------------
__device__ float  g_residual[(size_t)NROWS * DIM];
__device__ float  g_quantized[(size_t)NROWS * DIM];
__device__ float  g_norms[NQ * NV];
__device__ double g_norms64[NQ * NV];
__device__ int    g_indices[NROWS * NQ];
__device__ int    g_nflag[NQ];
__device__ int    g_flaglist[NQ * NROWS];
__device__ __align__(256) __half g_Ahi[(size_t)NROWS * DIM];        // 48 MB
__device__ __align__(256) __half g_Bhi[(size_t)NQ * NV * DIM];      // 25 MB
__device__ float4 g_part[(size_t)NROWS * NSEG];                     // 64 MB

// ---------------- PTX helpers ------------------------------------------------------
__device__ __forceinline__ uint32_t smem_u32(const void* p) {
    uint32_t a;
    asm("{ .reg .u64 t; cvta.to.shared.u64 t, %1; cvt.u32.u64 %0, t; }" : "=r"(a) : "l"(p));
    return a;
}
__device__ __forceinline__ void cp16(uint32_t s, const void* g) {
    asm volatile("cp.async.cg.shared.global [%0], [%1], 16;" :: "r"(s), "l"(g));
}
__device__ __forceinline__ void cp_commit() { asm volatile("cp.async.commit_group;"); }
template <int N>
__device__ __forceinline__ void cp_wait() { asm volatile("cp.async.wait_group %0;" :: "n"(N) : "memory"); }

__device__ __forceinline__ void ldm_x4(uint32_t* r, uint32_t a) {
    asm volatile("ldmatrix.sync.aligned.m8n8.x4.shared.b16 {%0,%1,%2,%3}, [%4];"
                 : "=r"(r[0]), "=r"(r[1]), "=r"(r[2]), "=r"(r[3]) : "r"(a));
}
__device__ __forceinline__ void ldm_x2(uint32_t* r, uint32_t a) {
    asm volatile("ldmatrix.sync.aligned.m8n8.x2.shared.b16 {%0,%1}, [%2];"
                 : "=r"(r[0]), "=r"(r[1]) : "r"(a));
}
__device__ __forceinline__ void mma16816(float* d, const uint32_t* a, const uint32_t* b) {
    asm volatile("mma.sync.aligned.m16n8k16.row.col.f32.f16.f16.f32 "
                 "{%0,%1,%2,%3}, {%4,%5,%6,%7}, {%8,%9}, {%0,%1,%2,%3};"
                 : "+f"(d[0]), "+f"(d[1]), "+f"(d[2]), "+f"(d[3])
                 : "r"(a[0]), "r"(a[1]), "r"(a[2]), "r"(a[3]), "r"(b[0]), "r"(b[1]));
}

__device__ __forceinline__ void store_hi4(__half* base, int c, float4 r) {
    *(__half2*)(base + c)     = __halves2half2(__float2half_rn(r.x), __float2half_rn(r.y));
    *(__half2*)(base + c + 2) = __halves2half2(__float2half_rn(r.z), __float2half_rn(r.w));
}

// ---------------- ||c||^2 per codeword (fp64 + fp32 copy) --------------------------
__global__ void norms_kernel(const float* __restrict__ cb) {
    int w = (blockIdx.x * blockDim.x + threadIdx.x) >> 5;
    int lane = threadIdx.x & 31;
    if (w >= NQ * NV) return;
    const float* c = cb + (size_t)w * DIM;
    double s = 0.0;
    #pragma unroll 4
    for (int d = lane; d < DIM; d += 32) {
        double v = (double)__ldg(c + d);
        s = fma(v, v, s);
    }
    #pragma unroll
    for (int o = 16; o; o >>= 1) s += __shfl_xor_sync(0xffffffffu, s, o);
    if (lane == 0) { g_norms64[w] = s; g_norms[w] = (float)s; }
}

// ---------------- residual = x (+ fp16 hi), quantized = 0, flags = 0 ----------------
__global__ void init_kernel(const float* __restrict__ x) {
    size_t i = (size_t)blockIdx.x * blockDim.x + threadIdx.x;
    if (i < NQ) g_nflag[i] = 0;
    if (i >= (size_t)NROWS * DIM / 4) return;
    float4 v = ((const float4*)x)[i];
    ((float4*)g_residual)[i] = v;
    ((float4*)g_quantized)[i] = make_float4(0.f, 0.f, 0.f, 0.f);
    int row = (int)(i / (DIM / 4));
    int c = (int)(i - (size_t)row * (DIM / 4)) * 4;
    store_hi4(g_Ahi + (size_t)row * DIM, c, v);
}

// ---------------- codebooks -> fp16 (once) -------------------------------------------
__global__ void convB_kernel(const float* __restrict__ cb) {
    int i = blockIdx.x * blockDim.x + threadIdx.x;
    if (i >= NQ * NV * (DIM / 4)) return;
    float4 v = *(const float4*)(cb + (size_t)i * 4);
    store_hi4(g_Bhi, i * 4, v);
}

// ---------------- mma.sync screen GEMM + per-row/segment top-2 ----------------------
// grid = MT2*NT2 (nt fastest), 256 threads = 8 warps (2m x 4n), warp tile 64x32
// 3-buffer cp.async ring, BK=64, one __syncthreads per stage.
__global__ void __launch_bounds__(256, 2)
score_gemm_kernel(int q) {
    extern __shared__ char dyn[];
    __shared__ float snorm[GBN];
    const uint32_t sbase = smem_u32(dyn);

    const int tid = threadIdx.x;
    const int wid = tid >> 5;
    const int lane = tid & 31;
    const int nt = blockIdx.x & (NT2 - 1);
    const int mt = blockIdx.x >> 5;
    const int block_m = mt * GBM;
    const int ncol0 = nt * GBN;
    const int warp_m = (wid >> 2) * 64;
    const int warp_n = (wid & 3) * 32;

    if (tid < GBN) snorm[tid] = g_norms[q * NV + ncol0 + tid];

    const char* Abase = (const char*)g_Ahi + (size_t)block_m * DIM * 2;
    const char* Bbase = (const char*)(g_Bhi + (size_t)q * NV * DIM)
                        + (size_t)ncol0 * DIM * 2;

    auto issue = [&](int s) {
        const int b = s % NBUF;
        const int k0 = s * BK;
        const uint32_t dA = sbase + b * (2 * BUFSZ);
        const uint32_t dB = dA + BUFSZ;
        const char* Ab = Abase + (size_t)k0 * 2;
        const char* Bb = Bbase + (size_t)k0 * 2;
        #pragma unroll
        for (int i = 0; i < 4; i++) {                 // 1024 16B chunks for A
            int ch = tid + i * 256;
            int r = ch >> 3, c16 = (ch & 7) * 16;
            cp16(dA + r * SROWB + c16, Ab + (size_t)r * (DIM * 2) + c16);
        }
        #pragma unroll
        for (int i = 0; i < 4; i++) {                 // 1024 16B chunks for B
            int ch = tid + i * 256;
            int r = ch >> 3, c16 = (ch & 7) * 16;
            cp16(dB + r * SROWB + c16, Bb + (size_t)r * (DIM * 2) + c16);
        }
        cp_commit();
    };

    float acc[4][4][4];
    #pragma unroll
    for (int im = 0; im < 4; im++)
        #pragma unroll
        for (int in = 0; in < 4; in++)
            #pragma unroll
            for (int e = 0; e < 4; e++) acc[im][in][e] = 0.f;

    issue(0);
    issue(1);

    const int arow = lane & 15;
    const int acolh = (lane >> 4) * 8;
    const int brow = lane & 7;
    const int bcolh = ((lane >> 3) & 1) * 8;

    #pragma unroll 1
    for (int s = 0; s < NSTG; ++s) {
        if (s < NSTG - 1) cp_wait<1>(); else cp_wait<0>();
        __syncthreads();
        if (s + 2 < NSTG) issue(s + 2);   // writes buf (s+2)%3 (= stage s-1's, done)

        const uint32_t aB = sbase + (s % NBUF) * (2 * BUFSZ);
        const uint32_t bB = aB + BUFSZ;
        #pragma unroll
        for (int kk = 0; kk < 4; kk++) {
            const int k0 = kk * 16;
            uint32_t afr[4][4];
            #pragma unroll
            for (int im = 0; im < 4; im++) {
                uint32_t addr = aB + (warp_m + im * 16 + arow) * SROWB + (k0 + acolh) * 2;
                ldm_x4(afr[im], addr);
            }
            #pragma unroll
            for (int in = 0; in < 4; in++) {
                uint32_t bfr[2];
                uint32_t addr = bB + (warp_n + in * 8 + brow) * SROWB + (k0 + bcolh) * 2;
                ldm_x2(bfr, addr);
                #pragma unroll
                for (int im = 0; im < 4; im++) mma16816(acc[im][in], afr[im], bfr);
            }
        }
    }

    // epilogue: per-row top-2 over this warp's 32 cols; quad-merge; write partials.
    const int seg = nt * 4 + (wid & 3);
    #pragma unroll
    for (int im = 0; im < 4; im++) {
        float t1a = -1e30f, t2a = -1e30f, t1b = -1e30f, t2b = -1e30f;
        int i1a = 0, i1b = 0;
        #pragma unroll
        for (int in = 0; in < 4; in++) {
            int c = warp_n + in * 8 + (lane & 3) * 2;
            float n0 = snorm[c], n1 = snorm[c + 1];
            float sa0 = fmaf(2.f, acc[im][in][0], -n0);
            float sa1 = fmaf(2.f, acc[im][in][1], -n1);
            float sb0 = fmaf(2.f, acc[im][in][2], -n0);
            float sb1 = fmaf(2.f, acc[im][in][3], -n1);
            int gc = ncol0 + c;
            if (sa0 > t1a) { t2a = t1a; t1a = sa0; i1a = gc; } else if (sa0 > t2a) t2a = sa0;
            if (sa1 > t1a) { t2a = t1a; t1a = sa1; i1a = gc + 1; } else if (sa1 > t2a) t2a = sa1;
            if (sb0 > t1b) { t2b = t1b; t1b = sb0; i1b = gc; } else if (sb0 > t2b) t2b = sb0;
            if (sb1 > t1b) { t2b = t1b; t1b = sb1; i1b = gc + 1; } else if (sb1 > t2b) t2b = sb1;
        }
        #pragma unroll
        for (int o = 1; o < 4; o <<= 1) {
            float u1 = __shfl_xor_sync(0xffffffffu, t1a, o);
            float u2 = __shfl_xor_sync(0xffffffffu, t2a, o);
            int   ui = __shfl_xor_sync(0xffffffffu, i1a, o);
            if (u1 > t1a || (u1 == t1a && ui < i1a)) { t2a = fmaxf(t1a, u2); t1a = u1; i1a = ui; }
            else t2a = fmaxf(t2a, u1);
            float v1 = __shfl_xor_sync(0xffffffffu, t1b, o);
            float v2 = __shfl_xor_sync(0xffffffffu, t2b, o);
            int   vi = __shfl_xor_sync(0xffffffffu, i1b, o);
            if (v1 > t1b || (v1 == t1b && vi < i1b)) { t2b = fmaxf(t1b, v2); t1b = v1; i1b = vi; }
            else t2b = fmaxf(t2b, v1);
        }
        if ((lane & 3) == 0) {
            int rA = block_m + warp_m + im * 16 + (lane >> 2);
            g_part[(size_t)rA * NSEG + seg] = make_float4(t1a, t2a, __int_as_float(i1a), 0.f);
            g_part[(size_t)(rA + 8) * NSEG + seg] = make_float4(t1b, t2b, __int_as_float(i1b), 0.f);
        }
    }
}

// ---------------- merge partials -> global top-2, index, flag list ------------------
__global__ void merge_kernel(int q) {
    int row = blockIdx.x * blockDim.x + threadIdx.x;
    if (row >= NROWS) return;
    float b1 = -1e30f, b2 = -1e30f;
    int bi = 0;
    const float4* p = &g_part[(size_t)row * NSEG];
    #pragma unroll 8
    for (int s = 0; s < NSEG; s++) {
        float4 v = p[s];   // segments ascending in col index: first-max-wins
        if (v.x > b1) { b2 = fmaxf(b1, v.y); b1 = v.x; bi = __float_as_int(v.z); }
        else          { b2 = fmaxf(b2, v.x); }
    }
    g_indices[row * NQ + q] = bi;
    if (b1 - b2 < DELTA) {
        int pos = atomicAdd(&g_nflag[q], 1);
        g_flaglist[q * NROWS + pos] = row;
    }
}

// ---------------- fp64 exhaustive refine for flagged rows ---------------------------
__global__ void __launch_bounds__(256, 1)
refine_kernel(const float* __restrict__ cb, int q) {
    __shared__ float  rsm[DIM];
    __shared__ double sred[256];
    __shared__ int    ired[256];

    const int tid = threadIdx.x;
    const int nf = g_nflag[q];

    for (int jj = blockIdx.x; jj < nf; jj += gridDim.x) {
        const int row = g_flaglist[q * NROWS + jj];
        for (int d = tid; d < DIM; d += 256) rsm[d] = g_residual[(size_t)row * DIM + d];
        __syncthreads();

        double best = -1e300;
        int bidx = 0;
        for (int v = tid; v < NV; v += 256) {
            const float4* cv = (const float4*)(cb + (size_t)v * DIM);
            double a0 = 0, a1 = 0, a2 = 0, a3 = 0, a4 = 0, a5 = 0, a6 = 0, a7 = 0;
            #pragma unroll 4
            for (int t = 0; t < DIM / 4; t += 2) {
                float4 c0 = __ldg(cv + t);
                float4 c1 = __ldg(cv + t + 1);
                const float4 r0 = *(const float4*)&rsm[4 * t];
                const float4 r1 = *(const float4*)&rsm[4 * t + 4];
                a0 = fma((double)r0.x, (double)c0.x, a0);
                a1 = fma((double)r0.y, (double)c0.y, a1);
                a2 = fma((double)r0.z, (double)c0.z, a2);
                a3 = fma((double)r0.w, (double)c0.w, a3);
                a4 = fma((double)r1.x, (double)c1.x, a4);
                a5 = fma((double)r1.y, (double)c1.y, a5);
                a6 = fma((double)r1.z, (double)c1.z, a6);
                a7 = fma((double)r1.w, (double)c1.w, a7);
            }
            double dot = ((a0 + a1) + (a2 + a3)) + ((a4 + a5) + (a6 + a7));
            double s = 2.0 * dot - g_norms64[q * NV + v];
            if (s > best) { best = s; bidx = v; }
        }
        sred[tid] = best; ired[tid] = bidx;
        __syncthreads();
        for (int o = 128; o; o >>= 1) {
            if (tid < o) {
                double so = sred[tid + o]; int vo = ired[tid + o];
                if (so > sred[tid] || (so == sred[tid] && vo < ired[tid])) {
                    sred[tid] = so; ired[tid] = vo;
                }
            }
            __syncthreads();
        }
        if (tid == 0) g_indices[row * NQ + q] = ired[0];
        __syncthreads();
    }
}

// ---------------- gather + residual/quantized update (+ fp16 hi of residual) --------
__global__ void update_kernel(const float* __restrict__ cb, int q) {
    int gid = blockIdx.x * blockDim.x + threadIdx.x;
    const int PR = DIM / 4;
    int row = gid / PR;
    if (row >= NROWS) return;
    int c = (gid - row * PR) << 2;
    int idx = __ldg(&g_indices[row * NQ + q]);
    const float4 cw = *(const float4*)(cb + (size_t)idx * DIM + c);
    size_t off = (size_t)row * DIM + c;
    float4 r = *(float4*)(g_residual + off);
    float4 z = *(float4*)(g_quantized + off);
    r.x -= cw.x; r.y -= cw.y; r.z -= cw.z; r.w -= cw.w;
    z.x += cw.x; z.y += cw.y; z.z += cw.z; z.w += cw.w;
    *(float4*)(g_residual + off) = r;
    *(float4*)(g_quantized + off) = z;
    store_hi4(g_Ahi + (size_t)row * DIM, c, r);  // next level's A
}

// ---------------- out = x + (quantized - x) -----------------------------------------
__global__ void finalize_kernel(const float* __restrict__ x, float* __restrict__ out) {
    size_t i = (size_t)blockIdx.x * blockDim.x + threadIdx.x;
    if (i >= (size_t)NROWS * DIM / 4) return;
    float4 xv = ((const float4*)x)[i];
    float4 qv = ((const float4*)g_quantized)[i];
    float4 o;
    o.x = xv.x + (qv.x - xv.x);
    o.y = xv.y + (qv.y - xv.y);
    o.z = xv.z + (qv.z - xv.z);
    o.w = xv.w + (qv.w - xv.w);
    ((float4*)out)[i] = o;
}

__global__ void idxout_kernel(float* __restrict__ out) {
    int i = blockIdx.x * blockDim.x + threadIdx.x;
    if (i < NROWS * NQ) out[i] = (float)g_indices[i];
}

extern "C" void kernel_launch(void* const* d_in, const int* in_sizes, int n_in,
                              void* d_out, int out_size) {
    const float* x  = (const float*)d_in[0];
    const float* cb = (const float*)d_in[1];
    float* out = (float*)d_out;

    cudaFuncSetAttribute(score_gemm_kernel,
                         cudaFuncAttributeMaxDynamicSharedMemorySize, SMEM_DYN);

    norms_kernel<<<(NQ * NV) / 8, 256>>>(cb);
    init_kernel<<<(NROWS * DIM / 4 + 255) / 256, 256>>>(x);
    convB_kernel<<<(NQ * NV * (DIM / 4) + 255) / 256, 256>>>(cb);

    for (int q = 0; q < NQ; q++) {
        const float* cbq = cb + (size_t)q * NV * DIM;
        score_gemm_kernel<<<MT2 * NT2, 256, SMEM_DYN>>>(q);
        merge_kernel<<<(NROWS + 255) / 256, 256>>>(q);
        refine_kernel<<<148, 256>>>(cbq, q);
        update_kernel<<<(NROWS * (DIM / 4) + 255) / 256, 256>>>(cbq, q);
    }

    finalize_kernel<<<(NROWS * DIM / 4 + 255) / 256, 256>>>(x, out);

    if (out_size >= NROWS * DIM + NROWS * NQ) {
        idxout_kernel<<<(NROWS * NQ + 255) / 256, 256>>>(out + (size_t)NROWS * DIM);
    }
}

// round 8
// speedup vs baseline: 4.1637x; 4.1637x over previous
#include <cuda_runtime.h>
#include <cuda_fp16.h>
#include <cstdint>

#define NROWS 32768
#define DIM   768
#define NQ    4
#define NV    4096
#define DELTA 0.25f      // screen flag threshold (fp16-GEMM error ~6.6 sigma)
#define TAU2  1e-3f      // fp32-refine -> fp64 threshold (~100 sigma of fp32 err)
#define MAXF2 4096       // stage-2 slot cap

#define GBM 128
#define GBN 128
#define KTOT 768
#define BK   64
#define NSTG (KTOT / BK)   // 12
#define NBUF 3
#define NT2  (NV / GBN)    // 32
#define MT2  (NROWS / GBM) // 256
#define SROW  72
#define SROWB 144
#define BUFSZ (128 * SROWB)
#define SMEM_DYN (NBUF * 2 * BUFSZ)
#define NSEG 128

// ---------------- scratch ---------------------------------------------------------
__device__ float  g_residual[(size_t)NROWS * DIM];
__device__ float  g_quantized[(size_t)NROWS * DIM];
__device__ float  g_norms[NQ * NV];
__device__ double g_norms64[NQ * NV];
__device__ int    g_indices[NROWS * NQ];
__device__ int    g_nflag[NQ];
__device__ int    g_flaglist[NQ * NROWS];
__device__ int    g_nflag2[NQ];
__device__ int    g_flag2[NQ * MAXF2];
__device__ double g_p2s[MAXF2 * 16];
__device__ int    g_p2i[MAXF2 * 16];
__device__ __align__(256) __half g_Ahi[(size_t)NROWS * DIM];
__device__ __align__(256) __half g_Bhi[(size_t)NQ * NV * DIM];
__device__ float4 g_part[(size_t)NROWS * NSEG];

// ---------------- PTX helpers ------------------------------------------------------
__device__ __forceinline__ uint32_t smem_u32(const void* p) {
    uint32_t a;
    asm("{ .reg .u64 t; cvta.to.shared.u64 t, %1; cvt.u32.u64 %0, t; }" : "=r"(a) : "l"(p));
    return a;
}
__device__ __forceinline__ void cp16(uint32_t s, const void* g) {
    asm volatile("cp.async.cg.shared.global [%0], [%1], 16;" :: "r"(s), "l"(g));
}
__device__ __forceinline__ void cp_commit() { asm volatile("cp.async.commit_group;"); }
template <int N>
__device__ __forceinline__ void cp_wait() { asm volatile("cp.async.wait_group %0;" :: "n"(N) : "memory"); }

__device__ __forceinline__ void ldm_x4(uint32_t* r, uint32_t a) {
    asm volatile("ldmatrix.sync.aligned.m8n8.x4.shared.b16 {%0,%1,%2,%3}, [%4];"
                 : "=r"(r[0]), "=r"(r[1]), "=r"(r[2]), "=r"(r[3]) : "r"(a));
}
__device__ __forceinline__ void ldm_x2(uint32_t* r, uint32_t a) {
    asm volatile("ldmatrix.sync.aligned.m8n8.x2.shared.b16 {%0,%1}, [%2];"
                 : "=r"(r[0]), "=r"(r[1]) : "r"(a));
}
__device__ __forceinline__ void mma16816(float* d, const uint32_t* a, const uint32_t* b) {
    asm volatile("mma.sync.aligned.m16n8k16.row.col.f32.f16.f16.f32 "
                 "{%0,%1,%2,%3}, {%4,%5,%6,%7}, {%8,%9}, {%0,%1,%2,%3};"
                 : "+f"(d[0]), "+f"(d[1]), "+f"(d[2]), "+f"(d[3])
                 : "r"(a[0]), "r"(a[1]), "r"(a[2]), "r"(a[3]), "r"(b[0]), "r"(b[1]));
}

__device__ __forceinline__ void store_hi4(__half* base, int c, float4 r) {
    *(__half2*)(base + c)     = __halves2half2(__float2half_rn(r.x), __float2half_rn(r.y));
    *(__half2*)(base + c + 2) = __halves2half2(__float2half_rn(r.z), __float2half_rn(r.w));
}

// ---------------- ||c||^2 per codeword (fp64 + fp32 copy) --------------------------
__global__ void norms_kernel(const float* __restrict__ cb) {
    int w = (blockIdx.x * blockDim.x + threadIdx.x) >> 5;
    int lane = threadIdx.x & 31;
    if (w >= NQ * NV) return;
    const float* c = cb + (size_t)w * DIM;
    double s = 0.0;
    #pragma unroll 4
    for (int d = lane; d < DIM; d += 32) {
        double v = (double)__ldg(c + d);
        s = fma(v, v, s);
    }
    #pragma unroll
    for (int o = 16; o; o >>= 1) s += __shfl_xor_sync(0xffffffffu, s, o);
    if (lane == 0) { g_norms64[w] = s; g_norms[w] = (float)s; }
}

// ---------------- residual = x (+ fp16 hi), quantized = 0, flags = 0 ----------------
__global__ void init_kernel(const float* __restrict__ x) {
    size_t i = (size_t)blockIdx.x * blockDim.x + threadIdx.x;
    if (i < NQ) { g_nflag[i] = 0; g_nflag2[i] = 0; }
    if (i >= (size_t)NROWS * DIM / 4) return;
    float4 v = ((const float4*)x)[i];
    ((float4*)g_residual)[i] = v;
    ((float4*)g_quantized)[i] = make_float4(0.f, 0.f, 0.f, 0.f);
    int row = (int)(i / (DIM / 4));
    int c = (int)(i - (size_t)row * (DIM / 4)) * 4;
    store_hi4(g_Ahi + (size_t)row * DIM, c, v);
}

// ---------------- codebooks -> fp16 (once) -------------------------------------------
__global__ void convB_kernel(const float* __restrict__ cb) {
    int i = blockIdx.x * blockDim.x + threadIdx.x;
    if (i >= NQ * NV * (DIM / 4)) return;
    float4 v = *(const float4*)(cb + (size_t)i * 4);
    store_hi4(g_Bhi, i * 4, v);
}

// ---------------- mma.sync screen GEMM + per-row/segment top-2 ----------------------
__global__ void __launch_bounds__(256, 2)
score_gemm_kernel(int q) {
    extern __shared__ char dyn[];
    __shared__ float snorm[GBN];
    const uint32_t sbase = smem_u32(dyn);

    const int tid = threadIdx.x;
    const int wid = tid >> 5;
    const int lane = tid & 31;
    const int nt = blockIdx.x & (NT2 - 1);
    const int mt = blockIdx.x >> 5;
    const int block_m = mt * GBM;
    const int ncol0 = nt * GBN;
    const int warp_m = (wid >> 2) * 64;
    const int warp_n = (wid & 3) * 32;

    if (tid < GBN) snorm[tid] = g_norms[q * NV + ncol0 + tid];

    const char* Abase = (const char*)g_Ahi + (size_t)block_m * DIM * 2;
    const char* Bbase = (const char*)(g_Bhi + (size_t)q * NV * DIM)
                        + (size_t)ncol0 * DIM * 2;

    auto issue = [&](int s) {
        const int b = s % NBUF;
        const int k0 = s * BK;
        const uint32_t dA = sbase + b * (2 * BUFSZ);
        const uint32_t dB = dA + BUFSZ;
        const char* Ab = Abase + (size_t)k0 * 2;
        const char* Bb = Bbase + (size_t)k0 * 2;
        #pragma unroll
        for (int i = 0; i < 4; i++) {
            int ch = tid + i * 256;
            int r = ch >> 3, c16 = (ch & 7) * 16;
            cp16(dA + r * SROWB + c16, Ab + (size_t)r * (DIM * 2) + c16);
        }
        #pragma unroll
        for (int i = 0; i < 4; i++) {
            int ch = tid + i * 256;
            int r = ch >> 3, c16 = (ch & 7) * 16;
            cp16(dB + r * SROWB + c16, Bb + (size_t)r * (DIM * 2) + c16);
        }
        cp_commit();
    };

    float acc[4][4][4];
    #pragma unroll
    for (int im = 0; im < 4; im++)
        #pragma unroll
        for (int in = 0; in < 4; in++)
            #pragma unroll
            for (int e = 0; e < 4; e++) acc[im][in][e] = 0.f;

    issue(0);
    issue(1);

    const int arow = lane & 15;
    const int acolh = (lane >> 4) * 8;
    const int brow = lane & 7;
    const int bcolh = ((lane >> 3) & 1) * 8;

    #pragma unroll 1
    for (int s = 0; s < NSTG; ++s) {
        if (s < NSTG - 1) cp_wait<1>(); else cp_wait<0>();
        __syncthreads();
        if (s + 2 < NSTG) issue(s + 2);

        const uint32_t aB = sbase + (s % NBUF) * (2 * BUFSZ);
        const uint32_t bB = aB + BUFSZ;
        #pragma unroll
        for (int kk = 0; kk < 4; kk++) {
            const int k0 = kk * 16;
            uint32_t afr[4][4];
            #pragma unroll
            for (int im = 0; im < 4; im++) {
                uint32_t addr = aB + (warp_m + im * 16 + arow) * SROWB + (k0 + acolh) * 2;
                ldm_x4(afr[im], addr);
            }
            #pragma unroll
            for (int in = 0; in < 4; in++) {
                uint32_t bfr[2];
                uint32_t addr = bB + (warp_n + in * 8 + brow) * SROWB + (k0 + bcolh) * 2;
                ldm_x2(bfr, addr);
                #pragma unroll
                for (int im = 0; im < 4; im++) mma16816(acc[im][in], afr[im], bfr);
            }
        }
    }

    const int seg = nt * 4 + (wid & 3);
    #pragma unroll
    for (int im = 0; im < 4; im++) {
        float t1a = -1e30f, t2a = -1e30f, t1b = -1e30f, t2b = -1e30f;
        int i1a = 0, i1b = 0;
        #pragma unroll
        for (int in = 0; in < 4; in++) {
            int c = warp_n + in * 8 + (lane & 3) * 2;
            float n0 = snorm[c], n1 = snorm[c + 1];
            float sa0 = fmaf(2.f, acc[im][in][0], -n0);
            float sa1 = fmaf(2.f, acc[im][in][1], -n1);
            float sb0 = fmaf(2.f, acc[im][in][2], -n0);
            float sb1 = fmaf(2.f, acc[im][in][3], -n1);
            int gc = ncol0 + c;
            if (sa0 > t1a) { t2a = t1a; t1a = sa0; i1a = gc; } else if (sa0 > t2a) t2a = sa0;
            if (sa1 > t1a) { t2a = t1a; t1a = sa1; i1a = gc + 1; } else if (sa1 > t2a) t2a = sa1;
            if (sb0 > t1b) { t2b = t1b; t1b = sb0; i1b = gc; } else if (sb0 > t2b) t2b = sb0;
            if (sb1 > t1b) { t2b = t1b; t1b = sb1; i1b = gc + 1; } else if (sb1 > t2b) t2b = sb1;
        }
        #pragma unroll
        for (int o = 1; o < 4; o <<= 1) {
            float u1 = __shfl_xor_sync(0xffffffffu, t1a, o);
            float u2 = __shfl_xor_sync(0xffffffffu, t2a, o);
            int   ui = __shfl_xor_sync(0xffffffffu, i1a, o);
            if (u1 > t1a || (u1 == t1a && ui < i1a)) { t2a = fmaxf(t1a, u2); t1a = u1; i1a = ui; }
            else t2a = fmaxf(t2a, u1);
            float v1 = __shfl_xor_sync(0xffffffffu, t1b, o);
            float v2 = __shfl_xor_sync(0xffffffffu, t2b, o);
            int   vi = __shfl_xor_sync(0xffffffffu, i1b, o);
            if (v1 > t1b || (v1 == t1b && vi < i1b)) { t2b = fmaxf(t1b, v2); t1b = v1; i1b = vi; }
            else t2b = fmaxf(t2b, v1);
        }
        if ((lane & 3) == 0) {
            int rA = block_m + warp_m + im * 16 + (lane >> 2);
            g_part[(size_t)rA * NSEG + seg] = make_float4(t1a, t2a, __int_as_float(i1a), 0.f);
            g_part[(size_t)(rA + 8) * NSEG + seg] = make_float4(t1b, t2b, __int_as_float(i1b), 0.f);
        }
    }
}

// ---------------- merge partials -> index + screen flag list ------------------------
__global__ void merge_kernel(int q) {
    int row = blockIdx.x * blockDim.x + threadIdx.x;
    if (row >= NROWS) return;
    float b1 = -1e30f, b2 = -1e30f;
    int bi = 0;
    const float4* p = &g_part[(size_t)row * NSEG];
    #pragma unroll 8
    for (int s = 0; s < NSEG; s++) {
        float4 v = p[s];
        if (v.x > b1) { b2 = fmaxf(b1, v.y); b1 = v.x; bi = __float_as_int(v.z); }
        else          { b2 = fmaxf(b2, v.x); }
    }
    g_indices[row * NQ + q] = bi;
    if (b1 - b2 < DELTA) {
        int pos = atomicAdd(&g_nflag[q], 1);
        g_flaglist[q * NROWS + pos] = row;
    }
}

// ---------------- stage-1: fp32 exhaustive refine for flagged rows ------------------
__global__ void __launch_bounds__(256, 1)
refine32_kernel(const float* __restrict__ cb, int q) {
    __shared__ float rsm[DIM];
    __shared__ float ss1[256], ss2[256];
    __shared__ int   si1[256];

    const int tid = threadIdx.x;
    const int nf = g_nflag[q];

    for (int jj = blockIdx.x; jj < nf; jj += gridDim.x) {
        const int row = g_flaglist[q * NROWS + jj];
        for (int d = tid; d < DIM; d += 256) rsm[d] = g_residual[(size_t)row * DIM + d];
        __syncthreads();

        float b1 = -1e30f, b2 = -1e30f;
        int bi = 0;
        for (int v = tid; v < NV; v += 256) {
            const float4* cv = (const float4*)(cb + (size_t)v * DIM);
            float a0 = 0, a1 = 0, a2 = 0, a3 = 0, a4 = 0, a5 = 0, a6 = 0, a7 = 0;
            #pragma unroll 4
            for (int t = 0; t < DIM / 4; t += 2) {
                float4 c0 = __ldg(cv + t);
                float4 c1 = __ldg(cv + t + 1);
                const float4 r0 = *(const float4*)&rsm[4 * t];
                const float4 r1 = *(const float4*)&rsm[4 * t + 4];
                a0 = fmaf(r0.x, c0.x, a0); a1 = fmaf(r0.y, c0.y, a1);
                a2 = fmaf(r0.z, c0.z, a2); a3 = fmaf(r0.w, c0.w, a3);
                a4 = fmaf(r1.x, c1.x, a4); a5 = fmaf(r1.y, c1.y, a5);
                a6 = fmaf(r1.z, c1.z, a6); a7 = fmaf(r1.w, c1.w, a7);
            }
            float dot = ((a0 + a1) + (a2 + a3)) + ((a4 + a5) + (a6 + a7));
            float s = fmaf(2.f, dot, -g_norms[q * NV + v]);
            if (s > b1) { b2 = b1; b1 = s; bi = v; }   // ascending v: first max wins
            else if (s > b2) b2 = s;
        }
        ss1[tid] = b1; ss2[tid] = b2; si1[tid] = bi;
        __syncthreads();
        for (int o = 128; o; o >>= 1) {
            if (tid < o) {
                float o1 = ss1[tid + o], o2 = ss2[tid + o];
                int   oi = si1[tid + o];
                if (o1 > ss1[tid] || (o1 == ss1[tid] && oi < si1[tid])) {
                    ss2[tid] = fmaxf(ss1[tid], o2);
                    ss1[tid] = o1; si1[tid] = oi;
                } else {
                    ss2[tid] = fmaxf(ss2[tid], o1);
                }
            }
            __syncthreads();
        }
        if (tid == 0) {
            g_indices[row * NQ + q] = si1[0];
            if (ss1[0] - ss2[0] < TAU2) {
                int pos = atomicAdd(&g_nflag2[q], 1);
                if (pos < MAXF2) g_flag2[q * MAXF2 + pos] = row;
            }
        }
        __syncthreads();
    }
}

// ---------------- stage-2a: fp64 per (row, 256-codeword chunk) -----------------------
__global__ void __launch_bounds__(256, 1)
refine64_chunk_kernel(const float* __restrict__ cb, int q) {
    __shared__ float  rsm[DIM];
    __shared__ double sred[256];
    __shared__ int    ired[256];

    const int tid = threadIdx.x;
    int nf2 = g_nflag2[q];
    if (nf2 > MAXF2) nf2 = MAXF2;
    const int nwork = nf2 * 16;

    for (int w = blockIdx.x; w < nwork; w += gridDim.x) {
        const int slot = w >> 4;
        const int chunk = w & 15;
        const int row = g_flag2[q * MAXF2 + slot];
        for (int d = tid; d < DIM; d += 256) rsm[d] = g_residual[(size_t)row * DIM + d];
        __syncthreads();

        const int v = chunk * 256 + tid;   // one codeword per thread
        const float4* cv = (const float4*)(cb + (size_t)v * DIM);
        double a0 = 0, a1 = 0, a2 = 0, a3 = 0, a4 = 0, a5 = 0, a6 = 0, a7 = 0;
        #pragma unroll 4
        for (int t = 0; t < DIM / 4; t += 2) {
            float4 c0 = __ldg(cv + t);
            float4 c1 = __ldg(cv + t + 1);
            const float4 r0 = *(const float4*)&rsm[4 * t];
            const float4 r1 = *(const float4*)&rsm[4 * t + 4];
            a0 = fma((double)r0.x, (double)c0.x, a0);
            a1 = fma((double)r0.y, (double)c0.y, a1);
            a2 = fma((double)r0.z, (double)c0.z, a2);
            a3 = fma((double)r0.w, (double)c0.w, a3);
            a4 = fma((double)r1.x, (double)c1.x, a4);
            a5 = fma((double)r1.y, (double)c1.y, a5);
            a6 = fma((double)r1.z, (double)c1.z, a6);
            a7 = fma((double)r1.w, (double)c1.w, a7);
        }
        double dot = ((a0 + a1) + (a2 + a3)) + ((a4 + a5) + (a6 + a7));
        sred[tid] = 2.0 * dot - g_norms64[q * NV + v];
        ired[tid] = v;
        __syncthreads();
        for (int o = 128; o; o >>= 1) {
            if (tid < o) {
                double so = sred[tid + o]; int vo = ired[tid + o];
                if (so > sred[tid] || (so == sred[tid] && vo < ired[tid])) {
                    sred[tid] = so; ired[tid] = vo;
                }
            }
            __syncthreads();
        }
        if (tid == 0) { g_p2s[slot * 16 + chunk] = sred[0]; g_p2i[slot * 16 + chunk] = ired[0]; }
        __syncthreads();
    }
}

// ---------------- stage-2b: reduce chunk winners -> final index ----------------------
__global__ void refine64_reduce_kernel(int q) {
    int slot = blockIdx.x * blockDim.x + threadIdx.x;
    int nf2 = g_nflag2[q];
    if (nf2 > MAXF2) nf2 = MAXF2;
    if (slot >= nf2) return;
    double b = -1e300;
    int bi = 0;
    #pragma unroll
    for (int c = 0; c < 16; c++) {      // ascending chunk -> ascending idx: first wins
        double s = g_p2s[slot * 16 + c];
        int i = g_p2i[slot * 16 + c];
        if (s > b || (s == b && i < bi)) { b = s; bi = i; }
    }
    const int row = g_flag2[q * MAXF2 + slot];
    g_indices[row * NQ + q] = bi;
}

// ---------------- gather + residual/quantized update (+ fp16 hi of residual) --------
__global__ void update_kernel(const float* __restrict__ cb, int q) {
    int gid = blockIdx.x * blockDim.x + threadIdx.x;
    const int PR = DIM / 4;
    int row = gid / PR;
    if (row >= NROWS) return;
    int c = (gid - row * PR) << 2;
    int idx = __ldg(&g_indices[row * NQ + q]);
    const float4 cw = *(const float4*)(cb + (size_t)idx * DIM + c);
    size_t off = (size_t)row * DIM + c;
    float4 r = *(float4*)(g_residual + off);
    float4 z = *(float4*)(g_quantized + off);
    r.x -= cw.x; r.y -= cw.y; r.z -= cw.z; r.w -= cw.w;
    z.x += cw.x; z.y += cw.y; z.z += cw.z; z.w += cw.w;
    *(float4*)(g_residual + off) = r;
    *(float4*)(g_quantized + off) = z;
    store_hi4(g_Ahi + (size_t)row * DIM, c, r);
}

// ---------------- out = x + (quantized - x) -----------------------------------------
__global__ void finalize_kernel(const float* __restrict__ x, float* __restrict__ out) {
    size_t i = (size_t)blockIdx.x * blockDim.x + threadIdx.x;
    if (i >= (size_t)NROWS * DIM / 4) return;
    float4 xv = ((const float4*)x)[i];
    float4 qv = ((const float4*)g_quantized)[i];
    float4 o;
    o.x = xv.x + (qv.x - xv.x);
    o.y = xv.y + (qv.y - xv.y);
    o.z = xv.z + (qv.z - xv.z);
    o.w = xv.w + (qv.w - xv.w);
    ((float4*)out)[i] = o;
}

__global__ void idxout_kernel(float* __restrict__ out) {
    int i = blockIdx.x * blockDim.x + threadIdx.x;
    if (i < NROWS * NQ) out[i] = (float)g_indices[i];
}

extern "C" void kernel_launch(void* const* d_in, const int* in_sizes, int n_in,
                              void* d_out, int out_size) {
    const float* x  = (const float*)d_in[0];
    const float* cb = (const float*)d_in[1];
    float* out = (float*)d_out;

    cudaFuncSetAttribute(score_gemm_kernel,
                         cudaFuncAttributeMaxDynamicSharedMemorySize, SMEM_DYN);

    norms_kernel<<<(NQ * NV) / 8, 256>>>(cb);
    init_kernel<<<(NROWS * DIM / 4 + 255) / 256, 256>>>(x);
    convB_kernel<<<(NQ * NV * (DIM / 4) + 255) / 256, 256>>>(cb);

    for (int q = 0; q < NQ; q++) {
        const float* cbq = cb + (size_t)q * NV * DIM;
        score_gemm_kernel<<<MT2 * NT2, 256, SMEM_DYN>>>(q);
        merge_kernel<<<(NROWS + 255) / 256, 256>>>(q);
        refine32_kernel<<<148, 256>>>(cbq, q);
        refine64_chunk_kernel<<<592, 256>>>(cbq, q);
        refine64_reduce_kernel<<<(MAXF2 + 255) / 256, 256>>>(q);
        update_kernel<<<(NROWS * (DIM / 4) + 255) / 256, 256>>>(cbq, q);
    }

    finalize_kernel<<<(NROWS * DIM / 4 + 255) / 256, 256>>>(x, out);

    if (out_size >= NROWS * DIM + NROWS * NQ) {
        idxout_kernel<<<(NROWS * NQ + 255) / 256, 256>>>(out + (size_t)NROWS * DIM);
    }
}

// round 9
// speedup vs baseline: 6.2044x; 1.4901x over previous
#include <cuda_runtime.h>
#include <cuda_fp16.h>
#include <cstdint>

#define NROWS 32768
#define DIM   768
#define NQ    4
#define NV    4096
#define DELTA 0.25f      // screen flag threshold (fp16-GEMM error ~8 sigma pairwise)
#define TAU2  1e-3f      // fp32-refine -> fp64 threshold (~100 sigma of fp32 err)
#define MAXF2 4096       // stage-2 slot cap
#define RB    8          // rows per refine32 batch

#define GBM 128
#define GBN 128
#define KTOT 768
#define BK   64
#define NSTG (KTOT / BK)   // 12
#define NBUF 3
#define NT2  (NV / GBN)    // 32
#define MT2  (NROWS / GBM) // 256
#define SROW  72
#define SROWB 144
#define BUFSZ (128 * SROWB)
#define SMEM_DYN (NBUF * 2 * BUFSZ)
#define NSEG 128

// ---------------- scratch ---------------------------------------------------------
__device__ float  g_residual[(size_t)NROWS * DIM];
__device__ float  g_quantized[(size_t)NROWS * DIM];
__device__ float  g_norms[NQ * NV];
__device__ double g_norms64[NQ * NV];
__device__ int    g_indices[NROWS * NQ];
__device__ int    g_nflag[NQ];
__device__ int    g_flaglist[NQ * NROWS];
__device__ int    g_nflag2[NQ];
__device__ int    g_flag2[NQ * MAXF2];
__device__ double g_p2s[MAXF2 * 16];
__device__ int    g_p2i[MAXF2 * 16];
__device__ __align__(256) __half g_Ahi[(size_t)NROWS * DIM];
__device__ __align__(256) __half g_Bhi[(size_t)NQ * NV * DIM];
__device__ float4 g_part[(size_t)NROWS * NSEG];

// ---------------- PTX helpers ------------------------------------------------------
__device__ __forceinline__ uint32_t smem_u32(const void* p) {
    uint32_t a;
    asm("{ .reg .u64 t; cvta.to.shared.u64 t, %1; cvt.u32.u64 %0, t; }" : "=r"(a) : "l"(p));
    return a;
}
__device__ __forceinline__ void cp16(uint32_t s, const void* g) {
    asm volatile("cp.async.cg.shared.global [%0], [%1], 16;" :: "r"(s), "l"(g));
}
__device__ __forceinline__ void cp_commit() { asm volatile("cp.async.commit_group;"); }
template <int N>
__device__ __forceinline__ void cp_wait() { asm volatile("cp.async.wait_group %0;" :: "n"(N) : "memory"); }

__device__ __forceinline__ void ldm_x4(uint32_t* r, uint32_t a) {
    asm volatile("ldmatrix.sync.aligned.m8n8.x4.shared.b16 {%0,%1,%2,%3}, [%4];"
                 : "=r"(r[0]), "=r"(r[1]), "=r"(r[2]), "=r"(r[3]) : "r"(a));
}
__device__ __forceinline__ void ldm_x2(uint32_t* r, uint32_t a) {
    asm volatile("ldmatrix.sync.aligned.m8n8.x2.shared.b16 {%0,%1}, [%2];"
                 : "=r"(r[0]), "=r"(r[1]) : "r"(a));
}
__device__ __forceinline__ void mma16816(float* d, const uint32_t* a, const uint32_t* b) {
    asm volatile("mma.sync.aligned.m16n8k16.row.col.f32.f16.f16.f32 "
                 "{%0,%1,%2,%3}, {%4,%5,%6,%7}, {%8,%9}, {%0,%1,%2,%3};"
                 : "+f"(d[0]), "+f"(d[1]), "+f"(d[2]), "+f"(d[3])
                 : "r"(a[0]), "r"(a[1]), "r"(a[2]), "r"(a[3]), "r"(b[0]), "r"(b[1]));
}

__device__ __forceinline__ void store_hi4(__half* base, int c, float4 r) {
    *(__half2*)(base + c)     = __halves2half2(__float2half_rn(r.x), __float2half_rn(r.y));
    *(__half2*)(base + c + 2) = __halves2half2(__float2half_rn(r.z), __float2half_rn(r.w));
}

// ---------------- ||c||^2 per codeword (fp64 + fp32 copy) --------------------------
__global__ void norms_kernel(const float* __restrict__ cb) {
    int w = (blockIdx.x * blockDim.x + threadIdx.x) >> 5;
    int lane = threadIdx.x & 31;
    if (w >= NQ * NV) return;
    const float* c = cb + (size_t)w * DIM;
    double s = 0.0;
    #pragma unroll 4
    for (int d = lane; d < DIM; d += 32) {
        double v = (double)__ldg(c + d);
        s = fma(v, v, s);
    }
    #pragma unroll
    for (int o = 16; o; o >>= 1) s += __shfl_xor_sync(0xffffffffu, s, o);
    if (lane == 0) { g_norms64[w] = s; g_norms[w] = (float)s; }
}

// ---------------- residual = x (+ fp16 hi), quantized = 0, flags = 0 ----------------
__global__ void init_kernel(const float* __restrict__ x) {
    size_t i = (size_t)blockIdx.x * blockDim.x + threadIdx.x;
    if (i < NQ) { g_nflag[i] = 0; g_nflag2[i] = 0; }
    if (i >= (size_t)NROWS * DIM / 4) return;
    float4 v = ((const float4*)x)[i];
    ((float4*)g_residual)[i] = v;
    ((float4*)g_quantized)[i] = make_float4(0.f, 0.f, 0.f, 0.f);
    int row = (int)(i / (DIM / 4));
    int c = (int)(i - (size_t)row * (DIM / 4)) * 4;
    store_hi4(g_Ahi + (size_t)row * DIM, c, v);
}

// ---------------- codebooks -> fp16 (once) -------------------------------------------
__global__ void convB_kernel(const float* __restrict__ cb) {
    int i = blockIdx.x * blockDim.x + threadIdx.x;
    if (i >= NQ * NV * (DIM / 4)) return;
    float4 v = *(const float4*)(cb + (size_t)i * 4);
    store_hi4(g_Bhi, i * 4, v);
}

// ---------------- mma.sync screen GEMM + per-row/segment top-2 ----------------------
__global__ void __launch_bounds__(256, 2)
score_gemm_kernel(int q) {
    extern __shared__ char dyn[];
    __shared__ float snorm[GBN];
    const uint32_t sbase = smem_u32(dyn);

    const int tid = threadIdx.x;
    const int wid = tid >> 5;
    const int lane = tid & 31;
    const int nt = blockIdx.x & (NT2 - 1);
    const int mt = blockIdx.x >> 5;
    const int block_m = mt * GBM;
    const int ncol0 = nt * GBN;
    const int warp_m = (wid >> 2) * 64;
    const int warp_n = (wid & 3) * 32;

    if (tid < GBN) snorm[tid] = g_norms[q * NV + ncol0 + tid];

    const char* Abase = (const char*)g_Ahi + (size_t)block_m * DIM * 2;
    const char* Bbase = (const char*)(g_Bhi + (size_t)q * NV * DIM)
                        + (size_t)ncol0 * DIM * 2;

    auto issue = [&](int s) {
        const int b = s % NBUF;
        const int k0 = s * BK;
        const uint32_t dA = sbase + b * (2 * BUFSZ);
        const uint32_t dB = dA + BUFSZ;
        const char* Ab = Abase + (size_t)k0 * 2;
        const char* Bb = Bbase + (size_t)k0 * 2;
        #pragma unroll
        for (int i = 0; i < 4; i++) {
            int ch = tid + i * 256;
            int r = ch >> 3, c16 = (ch & 7) * 16;
            cp16(dA + r * SROWB + c16, Ab + (size_t)r * (DIM * 2) + c16);
        }
        #pragma unroll
        for (int i = 0; i < 4; i++) {
            int ch = tid + i * 256;
            int r = ch >> 3, c16 = (ch & 7) * 16;
            cp16(dB + r * SROWB + c16, Bb + (size_t)r * (DIM * 2) + c16);
        }
        cp_commit();
    };

    float acc[4][4][4];
    #pragma unroll
    for (int im = 0; im < 4; im++)
        #pragma unroll
        for (int in = 0; in < 4; in++)
            #pragma unroll
            for (int e = 0; e < 4; e++) acc[im][in][e] = 0.f;

    issue(0);
    issue(1);

    const int arow = lane & 15;
    const int acolh = (lane >> 4) * 8;
    const int brow = lane & 7;
    const int bcolh = ((lane >> 3) & 1) * 8;

    #pragma unroll 1
    for (int s = 0; s < NSTG; ++s) {
        if (s < NSTG - 1) cp_wait<1>(); else cp_wait<0>();
        __syncthreads();
        if (s + 2 < NSTG) issue(s + 2);

        const uint32_t aB = sbase + (s % NBUF) * (2 * BUFSZ);
        const uint32_t bB = aB + BUFSZ;
        #pragma unroll
        for (int kk = 0; kk < 4; kk++) {
            const int k0 = kk * 16;
            uint32_t afr[4][4];
            #pragma unroll
            for (int im = 0; im < 4; im++) {
                uint32_t addr = aB + (warp_m + im * 16 + arow) * SROWB + (k0 + acolh) * 2;
                ldm_x4(afr[im], addr);
            }
            #pragma unroll
            for (int in = 0; in < 4; in++) {
                uint32_t bfr[2];
                uint32_t addr = bB + (warp_n + in * 8 + brow) * SROWB + (k0 + bcolh) * 2;
                ldm_x2(bfr, addr);
                #pragma unroll
                for (int im = 0; im < 4; im++) mma16816(acc[im][in], afr[im], bfr);
            }
        }
    }

    const int seg = nt * 4 + (wid & 3);
    #pragma unroll
    for (int im = 0; im < 4; im++) {
        float t1a = -1e30f, t2a = -1e30f, t1b = -1e30f, t2b = -1e30f;
        int i1a = 0, i1b = 0;
        #pragma unroll
        for (int in = 0; in < 4; in++) {
            int c = warp_n + in * 8 + (lane & 3) * 2;
            float n0 = snorm[c], n1 = snorm[c + 1];
            float sa0 = fmaf(2.f, acc[im][in][0], -n0);
            float sa1 = fmaf(2.f, acc[im][in][1], -n1);
            float sb0 = fmaf(2.f, acc[im][in][2], -n0);
            float sb1 = fmaf(2.f, acc[im][in][3], -n1);
            int gc = ncol0 + c;
            if (sa0 > t1a) { t2a = t1a; t1a = sa0; i1a = gc; } else if (sa0 > t2a) t2a = sa0;
            if (sa1 > t1a) { t2a = t1a; t1a = sa1; i1a = gc + 1; } else if (sa1 > t2a) t2a = sa1;
            if (sb0 > t1b) { t2b = t1b; t1b = sb0; i1b = gc; } else if (sb0 > t2b) t2b = sb0;
            if (sb1 > t1b) { t2b = t1b; t1b = sb1; i1b = gc + 1; } else if (sb1 > t2b) t2b = sb1;
        }
        #pragma unroll
        for (int o = 1; o < 4; o <<= 1) {
            float u1 = __shfl_xor_sync(0xffffffffu, t1a, o);
            float u2 = __shfl_xor_sync(0xffffffffu, t2a, o);
            int   ui = __shfl_xor_sync(0xffffffffu, i1a, o);
            if (u1 > t1a || (u1 == t1a && ui < i1a)) { t2a = fmaxf(t1a, u2); t1a = u1; i1a = ui; }
            else t2a = fmaxf(t2a, u1);
            float v1 = __shfl_xor_sync(0xffffffffu, t1b, o);
            float v2 = __shfl_xor_sync(0xffffffffu, t2b, o);
            int   vi = __shfl_xor_sync(0xffffffffu, i1b, o);
            if (v1 > t1b || (v1 == t1b && vi < i1b)) { t2b = fmaxf(t1b, v2); t1b = v1; i1b = vi; }
            else t2b = fmaxf(t2b, v1);
        }
        if ((lane & 3) == 0) {
            int rA = block_m + warp_m + im * 16 + (lane >> 2);
            g_part[(size_t)rA * NSEG + seg] = make_float4(t1a, t2a, __int_as_float(i1a), 0.f);
            g_part[(size_t)(rA + 8) * NSEG + seg] = make_float4(t1b, t2b, __int_as_float(i1b), 0.f);
        }
    }
}

// ---------------- merge partials -> index + screen flag list ------------------------
__global__ void merge_kernel(int q) {
    int row = blockIdx.x * blockDim.x + threadIdx.x;
    if (row >= NROWS) return;
    float b1 = -1e30f, b2 = -1e30f;
    int bi = 0;
    const float4* p = &g_part[(size_t)row * NSEG];
    #pragma unroll 8
    for (int s = 0; s < NSEG; s++) {
        float4 v = p[s];
        if (v.x > b1) { b2 = fmaxf(b1, v.y); b1 = v.x; bi = __float_as_int(v.z); }
        else          { b2 = fmaxf(b2, v.x); }
    }
    g_indices[row * NQ + q] = bi;
    if (b1 - b2 < DELTA) {
        int pos = atomicAdd(&g_nflag[q], 1);
        g_flaglist[q * NROWS + pos] = row;
    }
}

// ---------------- stage-1: fp32 batched exhaustive refine (RB rows/block) -----------
__global__ void __launch_bounds__(256, 2)
refine32_kernel(const float* __restrict__ cb, int q) {
    __shared__ float rsm[RB][DIM];
    __shared__ float ss1[256], ss2[256];
    __shared__ int   si1[256];
    __shared__ int   rows_s[RB];

    const int tid = threadIdx.x;
    const int nf = g_nflag[q];

    for (int batch = blockIdx.x * RB; batch < nf; batch += gridDim.x * RB) {
        const int nr = min(RB, nf - batch);
        if (tid < RB) {
            int j = min(tid, nr - 1);
            rows_s[tid] = g_flaglist[q * NROWS + batch + j];
        }
        __syncthreads();
        #pragma unroll
        for (int j = 0; j < RB; j++) {
            const float4* src = (const float4*)(g_residual + (size_t)rows_s[j] * DIM);
            for (int d = tid; d < DIM / 4; d += 256) ((float4*)rsm[j])[d] = src[d];
        }
        __syncthreads();

        float b1[RB], b2[RB];
        int bi[RB];
        #pragma unroll
        for (int j = 0; j < RB; j++) { b1[j] = -1e30f; b2[j] = -1e30f; bi[j] = 0; }

        for (int v = tid; v < NV; v += 256) {
            const float4* cv = (const float4*)(cb + (size_t)v * DIM);
            float acc[RB];
            #pragma unroll
            for (int j = 0; j < RB; j++) acc[j] = 0.f;
            #pragma unroll 2
            for (int t = 0; t < DIM / 4; t++) {
                float4 c = __ldg(cv + t);
                #pragma unroll
                for (int j = 0; j < RB; j++) {
                    float4 r = ((const float4*)rsm[j])[t];
                    acc[j] = fmaf(c.x, r.x, acc[j]);
                    acc[j] = fmaf(c.y, r.y, acc[j]);
                    acc[j] = fmaf(c.z, r.z, acc[j]);
                    acc[j] = fmaf(c.w, r.w, acc[j]);
                }
            }
            float nrm = g_norms[q * NV + v];
            #pragma unroll
            for (int j = 0; j < RB; j++) {
                float s = fmaf(2.f, acc[j], -nrm);
                if (s > b1[j]) { b2[j] = b1[j]; b1[j] = s; bi[j] = v; }  // ascending v
                else if (s > b2[j]) b2[j] = s;
            }
        }

        for (int j = 0; j < nr; j++) {
            ss1[tid] = b1[j]; ss2[tid] = b2[j]; si1[tid] = bi[j];
            __syncthreads();
            for (int o = 128; o; o >>= 1) {
                if (tid < o) {
                    float o1 = ss1[tid + o], o2 = ss2[tid + o];
                    int   oi = si1[tid + o];
                    if (o1 > ss1[tid] || (o1 == ss1[tid] && oi < si1[tid])) {
                        ss2[tid] = fmaxf(ss1[tid], o2);
                        ss1[tid] = o1; si1[tid] = oi;
                    } else {
                        ss2[tid] = fmaxf(ss2[tid], o1);
                    }
                }
                __syncthreads();
            }
            if (tid == 0) {
                int row = rows_s[j];
                g_indices[row * NQ + q] = si1[0];
                if (ss1[0] - ss2[0] < TAU2) {
                    int pos = atomicAdd(&g_nflag2[q], 1);
                    if (pos < MAXF2) g_flag2[q * MAXF2 + pos] = row;
                }
            }
            __syncthreads();
        }
    }
}

// ---------------- stage-2a: fp64 per (row, 256-codeword chunk) -----------------------
__global__ void __launch_bounds__(256, 1)
refine64_chunk_kernel(const float* __restrict__ cb, int q) {
    __shared__ float  rsm[DIM];
    __shared__ double sred[256];
    __shared__ int    ired[256];

    const int tid = threadIdx.x;
    int nf2 = g_nflag2[q];
    if (nf2 > MAXF2) nf2 = MAXF2;
    const int nwork = nf2 * 16;

    for (int w = blockIdx.x; w < nwork; w += gridDim.x) {
        const int slot = w >> 4;
        const int chunk = w & 15;
        const int row = g_flag2[q * MAXF2 + slot];
        for (int d = tid; d < DIM; d += 256) rsm[d] = g_residual[(size_t)row * DIM + d];
        __syncthreads();

        const int v = chunk * 256 + tid;
        const float4* cv = (const float4*)(cb + (size_t)v * DIM);
        double a0 = 0, a1 = 0, a2 = 0, a3 = 0, a4 = 0, a5 = 0, a6 = 0, a7 = 0;
        #pragma unroll 4
        for (int t = 0; t < DIM / 4; t += 2) {
            float4 c0 = __ldg(cv + t);
            float4 c1 = __ldg(cv + t + 1);
            const float4 r0 = *(const float4*)&rsm[4 * t];
            const float4 r1 = *(const float4*)&rsm[4 * t + 4];
            a0 = fma((double)r0.x, (double)c0.x, a0);
            a1 = fma((double)r0.y, (double)c0.y, a1);
            a2 = fma((double)r0.z, (double)c0.z, a2);
            a3 = fma((double)r0.w, (double)c0.w, a3);
            a4 = fma((double)r1.x, (double)c1.x, a4);
            a5 = fma((double)r1.y, (double)c1.y, a5);
            a6 = fma((double)r1.z, (double)c1.z, a6);
            a7 = fma((double)r1.w, (double)c1.w, a7);
        }
        double dot = ((a0 + a1) + (a2 + a3)) + ((a4 + a5) + (a6 + a7));
        sred[tid] = 2.0 * dot - g_norms64[q * NV + v];
        ired[tid] = v;
        __syncthreads();
        for (int o = 128; o; o >>= 1) {
            if (tid < o) {
                double so = sred[tid + o]; int vo = ired[tid + o];
                if (so > sred[tid] || (so == sred[tid] && vo < ired[tid])) {
                    sred[tid] = so; ired[tid] = vo;
                }
            }
            __syncthreads();
        }
        if (tid == 0) { g_p2s[slot * 16 + chunk] = sred[0]; g_p2i[slot * 16 + chunk] = ired[0]; }
        __syncthreads();
    }
}

// ---------------- stage-2b: reduce chunk winners -> final index ----------------------
__global__ void refine64_reduce_kernel(int q) {
    int slot = blockIdx.x * blockDim.x + threadIdx.x;
    int nf2 = g_nflag2[q];
    if (nf2 > MAXF2) nf2 = MAXF2;
    if (slot >= nf2) return;
    double b = -1e300;
    int bi = 0;
    #pragma unroll
    for (int c = 0; c < 16; c++) {
        double s = g_p2s[slot * 16 + c];
        int i = g_p2i[slot * 16 + c];
        if (s > b || (s == b && i < bi)) { b = s; bi = i; }
    }
    const int row = g_flag2[q * MAXF2 + slot];
    g_indices[row * NQ + q] = bi;
}

// ---------------- gather + residual/quantized update (+ fp16 hi of residual) --------
__global__ void update_kernel(const float* __restrict__ cb, int q) {
    int gid = blockIdx.x * blockDim.x + threadIdx.x;
    const int PR = DIM / 4;
    int row = gid / PR;
    if (row >= NROWS) return;
    int c = (gid - row * PR) << 2;
    int idx = __ldg(&g_indices[row * NQ + q]);
    const float4 cw = *(const float4*)(cb + (size_t)idx * DIM + c);
    size_t off = (size_t)row * DIM + c;
    float4 r = *(float4*)(g_residual + off);
    float4 z = *(float4*)(g_quantized + off);
    r.x -= cw.x; r.y -= cw.y; r.z -= cw.z; r.w -= cw.w;
    z.x += cw.x; z.y += cw.y; z.z += cw.z; z.w += cw.w;
    *(float4*)(g_residual + off) = r;
    *(float4*)(g_quantized + off) = z;
    store_hi4(g_Ahi + (size_t)row * DIM, c, r);
}

// ---------------- out = x + (quantized - x) -----------------------------------------
__global__ void finalize_kernel(const float* __restrict__ x, float* __restrict__ out) {
    size_t i = (size_t)blockIdx.x * blockDim.x + threadIdx.x;
    if (i >= (size_t)NROWS * DIM / 4) return;
    float4 xv = ((const float4*)x)[i];
    float4 qv = ((const float4*)g_quantized)[i];
    float4 o;
    o.x = xv.x + (qv.x - xv.x);
    o.y = xv.y + (qv.y - xv.y);
    o.z = xv.z + (qv.z - xv.z);
    o.w = xv.w + (qv.w - xv.w);
    ((float4*)out)[i] = o;
}

__global__ void idxout_kernel(float* __restrict__ out) {
    int i = blockIdx.x * blockDim.x + threadIdx.x;
    if (i < NROWS * NQ) out[i] = (float)g_indices[i];
}

extern "C" void kernel_launch(void* const* d_in, const int* in_sizes, int n_in,
                              void* d_out, int out_size) {
    const float* x  = (const float*)d_in[0];
    const float* cb = (const float*)d_in[1];
    float* out = (float*)d_out;

    cudaFuncSetAttribute(score_gemm_kernel,
                         cudaFuncAttributeMaxDynamicSharedMemorySize, SMEM_DYN);

    norms_kernel<<<(NQ * NV) / 8, 256>>>(cb);
    init_kernel<<<(NROWS * DIM / 4 + 255) / 256, 256>>>(x);
    convB_kernel<<<(NQ * NV * (DIM / 4) + 255) / 256, 256>>>(cb);

    for (int q = 0; q < NQ; q++) {
        const float* cbq = cb + (size_t)q * NV * DIM;
        score_gemm_kernel<<<MT2 * NT2, 256, SMEM_DYN>>>(q);
        merge_kernel<<<(NROWS + 255) / 256, 256>>>(q);
        refine32_kernel<<<448, 256>>>(cbq, q);
        refine64_chunk_kernel<<<592, 256>>>(cbq, q);
        refine64_reduce_kernel<<<(MAXF2 + 255) / 256, 256>>>(q);
        update_kernel<<<(NROWS * (DIM / 4) + 255) / 256, 256>>>(cbq, q);
    }

    finalize_kernel<<<(NROWS * DIM / 4 + 255) / 256, 256>>>(x, out);

    if (out_size >= NROWS * DIM + NROWS * NQ) {
        idxout_kernel<<<(NROWS * NQ + 255) / 256, 256>>>(out + (size_t)NROWS * DIM);
    }
}

// round 10
// speedup vs baseline: 6.4263x; 1.0358x over previous
#include <cuda_runtime.h>
#include <cuda_fp16.h>
#include <cstdint>

#define NROWS 32768
#define DIM   768
#define NQ    4
#define NV    4096
#define DELTA 0.16f      // screen flag threshold (5.2 sigma of fp16-GEMM pairwise err)
#define TAU2  1e-3f      // fp32-refine -> fp64 threshold
#define MAXF2 4096
#define RB    8          // rows per refine32 batch (4 packed pairs)

#define GBM 128
#define GBN 128
#define KTOT 768
#define BK   64
#define NSTG (KTOT / BK)   // 12
#define NBUF 3
#define NT2  (NV / GBN)    // 32
#define MT2  (NROWS / GBM) // 256
#define SROW  72
#define SROWB 144
#define BUFSZ (128 * SROWB)
#define SMEM_DYN (NBUF * 2 * BUFSZ)
#define NSEG 128

// ---------------- scratch ---------------------------------------------------------
__device__ float  g_residual[(size_t)NROWS * DIM];
__device__ float  g_quantized[(size_t)NROWS * DIM];
__device__ float  g_norms[NQ * NV];
__device__ double g_norms64[NQ * NV];
__device__ int    g_indices[NROWS * NQ];
__device__ int    g_nflag[NQ];
__device__ int    g_flaglist[NQ * NROWS];
__device__ int    g_nflag2[NQ];
__device__ int    g_flag2[NQ * MAXF2];
__device__ double g_p2s[MAXF2 * 16];
__device__ int    g_p2i[MAXF2 * 16];
__device__ __align__(256) __half g_Ahi[(size_t)NROWS * DIM];
__device__ __align__(256) __half g_Bhi[(size_t)NQ * NV * DIM];
__device__ float4 g_part[(size_t)NROWS * NSEG];

// ---------------- PTX helpers ------------------------------------------------------
__device__ __forceinline__ uint32_t smem_u32(const void* p) {
    uint32_t a;
    asm("{ .reg .u64 t; cvta.to.shared.u64 t, %1; cvt.u32.u64 %0, t; }" : "=r"(a) : "l"(p));
    return a;
}
__device__ __forceinline__ void cp16(uint32_t s, const void* g) {
    asm volatile("cp.async.cg.shared.global [%0], [%1], 16;" :: "r"(s), "l"(g));
}
__device__ __forceinline__ void cp_commit() { asm volatile("cp.async.commit_group;"); }
template <int N>
__device__ __forceinline__ void cp_wait() { asm volatile("cp.async.wait_group %0;" :: "n"(N) : "memory"); }

__device__ __forceinline__ void ldm_x4(uint32_t* r, uint32_t a) {
    asm volatile("ldmatrix.sync.aligned.m8n8.x4.shared.b16 {%0,%1,%2,%3}, [%4];"
                 : "=r"(r[0]), "=r"(r[1]), "=r"(r[2]), "=r"(r[3]) : "r"(a));
}
__device__ __forceinline__ void ldm_x2(uint32_t* r, uint32_t a) {
    asm volatile("ldmatrix.sync.aligned.m8n8.x2.shared.b16 {%0,%1}, [%2];"
                 : "=r"(r[0]), "=r"(r[1]) : "r"(a));
}
__device__ __forceinline__ void mma16816(float* d, const uint32_t* a, const uint32_t* b) {
    asm volatile("mma.sync.aligned.m16n8k16.row.col.f32.f16.f16.f32 "
                 "{%0,%1,%2,%3}, {%4,%5,%6,%7}, {%8,%9}, {%0,%1,%2,%3};"
                 : "+f"(d[0]), "+f"(d[1]), "+f"(d[2]), "+f"(d[3])
                 : "r"(a[0]), "r"(a[1]), "r"(a[2]), "r"(a[3]), "r"(b[0]), "r"(b[1]));
}

// packed f32x2 helpers (elementwise fp32 fma on a pair)
__device__ __forceinline__ unsigned long long pack2(float x, float y) {
    unsigned long long r;
    asm("mov.b64 %0, {%1,%2};" : "=l"(r) : "f"(x), "f"(y));
    return r;
}
__device__ __forceinline__ float2 unpack2(unsigned long long v) {
    float2 r;
    asm("mov.b64 {%0,%1}, %2;" : "=f"(r.x), "=f"(r.y) : "l"(v));
    return r;
}
__device__ __forceinline__ void fma2(unsigned long long& d,
                                     unsigned long long a,
                                     unsigned long long b) {
    asm("fma.rn.f32x2 %0, %1, %2, %0;" : "+l"(d) : "l"(a), "l"(b));
}

__device__ __forceinline__ void store_hi4(__half* base, int c, float4 r) {
    *(__half2*)(base + c)     = __halves2half2(__float2half_rn(r.x), __float2half_rn(r.y));
    *(__half2*)(base + c + 2) = __halves2half2(__float2half_rn(r.z), __float2half_rn(r.w));
}

// ---------------- ||c||^2 per codeword (fp64 + fp32 copy) --------------------------
__global__ void norms_kernel(const float* __restrict__ cb) {
    int w = (blockIdx.x * blockDim.x + threadIdx.x) >> 5;
    int lane = threadIdx.x & 31;
    if (w >= NQ * NV) return;
    const float* c = cb + (size_t)w * DIM;
    double s = 0.0;
    #pragma unroll 4
    for (int d = lane; d < DIM; d += 32) {
        double v = (double)__ldg(c + d);
        s = fma(v, v, s);
    }
    #pragma unroll
    for (int o = 16; o; o >>= 1) s += __shfl_xor_sync(0xffffffffu, s, o);
    if (lane == 0) { g_norms64[w] = s; g_norms[w] = (float)s; }
}

// ---------------- residual = x (+ fp16 hi), quantized = 0, flags = 0 ----------------
__global__ void init_kernel(const float* __restrict__ x) {
    size_t i = (size_t)blockIdx.x * blockDim.x + threadIdx.x;
    if (i < NQ) { g_nflag[i] = 0; g_nflag2[i] = 0; }
    if (i >= (size_t)NROWS * DIM / 4) return;
    float4 v = ((const float4*)x)[i];
    ((float4*)g_residual)[i] = v;
    ((float4*)g_quantized)[i] = make_float4(0.f, 0.f, 0.f, 0.f);
    int row = (int)(i / (DIM / 4));
    int c = (int)(i - (size_t)row * (DIM / 4)) * 4;
    store_hi4(g_Ahi + (size_t)row * DIM, c, v);
}

// ---------------- codebooks -> fp16 (once) -------------------------------------------
__global__ void convB_kernel(const float* __restrict__ cb) {
    int i = blockIdx.x * blockDim.x + threadIdx.x;
    if (i >= NQ * NV * (DIM / 4)) return;
    float4 v = *(const float4*)(cb + (size_t)i * 4);
    store_hi4(g_Bhi, i * 4, v);
}

// ---------------- mma.sync screen GEMM + per-row/segment top-2 ----------------------
__global__ void __launch_bounds__(256, 2)
score_gemm_kernel(int q) {
    extern __shared__ char dyn[];
    __shared__ float snorm[GBN];
    const uint32_t sbase = smem_u32(dyn);

    const int tid = threadIdx.x;
    const int wid = tid >> 5;
    const int lane = tid & 31;
    const int nt = blockIdx.x & (NT2 - 1);
    const int mt = blockIdx.x >> 5;
    const int block_m = mt * GBM;
    const int ncol0 = nt * GBN;
    const int warp_m = (wid >> 2) * 64;
    const int warp_n = (wid & 3) * 32;

    if (tid < GBN) snorm[tid] = g_norms[q * NV + ncol0 + tid];

    const char* Abase = (const char*)g_Ahi + (size_t)block_m * DIM * 2;
    const char* Bbase = (const char*)(g_Bhi + (size_t)q * NV * DIM)
                        + (size_t)ncol0 * DIM * 2;

    auto issue = [&](int s) {
        const int b = s % NBUF;
        const int k0 = s * BK;
        const uint32_t dA = sbase + b * (2 * BUFSZ);
        const uint32_t dB = dA + BUFSZ;
        const char* Ab = Abase + (size_t)k0 * 2;
        const char* Bb = Bbase + (size_t)k0 * 2;
        #pragma unroll
        for (int i = 0; i < 4; i++) {
            int ch = tid + i * 256;
            int r = ch >> 3, c16 = (ch & 7) * 16;
            cp16(dA + r * SROWB + c16, Ab + (size_t)r * (DIM * 2) + c16);
        }
        #pragma unroll
        for (int i = 0; i < 4; i++) {
            int ch = tid + i * 256;
            int r = ch >> 3, c16 = (ch & 7) * 16;
            cp16(dB + r * SROWB + c16, Bb + (size_t)r * (DIM * 2) + c16);
        }
        cp_commit();
    };

    float acc[4][4][4];
    #pragma unroll
    for (int im = 0; im < 4; im++)
        #pragma unroll
        for (int in = 0; in < 4; in++)
            #pragma unroll
            for (int e = 0; e < 4; e++) acc[im][in][e] = 0.f;

    issue(0);
    issue(1);

    const int arow = lane & 15;
    const int acolh = (lane >> 4) * 8;
    const int brow = lane & 7;
    const int bcolh = ((lane >> 3) & 1) * 8;

    #pragma unroll
    for (int s = 0; s < NSTG; ++s) {
        if (s < NSTG - 1) cp_wait<1>(); else cp_wait<0>();
        __syncthreads();
        if (s + 2 < NSTG) issue(s + 2);

        const uint32_t aB = sbase + (s % NBUF) * (2 * BUFSZ);
        const uint32_t bB = aB + BUFSZ;
        #pragma unroll
        for (int kk = 0; kk < 4; kk++) {
            const int k0 = kk * 16;
            uint32_t afr[4][4];
            #pragma unroll
            for (int im = 0; im < 4; im++) {
                uint32_t addr = aB + (warp_m + im * 16 + arow) * SROWB + (k0 + acolh) * 2;
                ldm_x4(afr[im], addr);
            }
            #pragma unroll
            for (int in = 0; in < 4; in++) {
                uint32_t bfr[2];
                uint32_t addr = bB + (warp_n + in * 8 + brow) * SROWB + (k0 + bcolh) * 2;
                ldm_x2(bfr, addr);
                #pragma unroll
                for (int im = 0; im < 4; im++) mma16816(acc[im][in], afr[im], bfr);
            }
        }
    }

    const int seg = nt * 4 + (wid & 3);
    #pragma unroll
    for (int im = 0; im < 4; im++) {
        float t1a = -1e30f, t2a = -1e30f, t1b = -1e30f, t2b = -1e30f;
        int i1a = 0, i1b = 0;
        #pragma unroll
        for (int in = 0; in < 4; in++) {
            int c = warp_n + in * 8 + (lane & 3) * 2;
            float n0 = snorm[c], n1 = snorm[c + 1];
            float sa0 = fmaf(2.f, acc[im][in][0], -n0);
            float sa1 = fmaf(2.f, acc[im][in][1], -n1);
            float sb0 = fmaf(2.f, acc[im][in][2], -n0);
            float sb1 = fmaf(2.f, acc[im][in][3], -n1);
            int gc = ncol0 + c;
            if (sa0 > t1a) { t2a = t1a; t1a = sa0; i1a = gc; } else if (sa0 > t2a) t2a = sa0;
            if (sa1 > t1a) { t2a = t1a; t1a = sa1; i1a = gc + 1; } else if (sa1 > t2a) t2a = sa1;
            if (sb0 > t1b) { t2b = t1b; t1b = sb0; i1b = gc; } else if (sb0 > t2b) t2b = sb0;
            if (sb1 > t1b) { t2b = t1b; t1b = sb1; i1b = gc + 1; } else if (sb1 > t2b) t2b = sb1;
        }
        #pragma unroll
        for (int o = 1; o < 4; o <<= 1) {
            float u1 = __shfl_xor_sync(0xffffffffu, t1a, o);
            float u2 = __shfl_xor_sync(0xffffffffu, t2a, o);
            int   ui = __shfl_xor_sync(0xffffffffu, i1a, o);
            if (u1 > t1a || (u1 == t1a && ui < i1a)) { t2a = fmaxf(t1a, u2); t1a = u1; i1a = ui; }
            else t2a = fmaxf(t2a, u1);
            float v1 = __shfl_xor_sync(0xffffffffu, t1b, o);
            float v2 = __shfl_xor_sync(0xffffffffu, t2b, o);
            int   vi = __shfl_xor_sync(0xffffffffu, i1b, o);
            if (v1 > t1b || (v1 == t1b && vi < i1b)) { t2b = fmaxf(t1b, v2); t1b = v1; i1b = vi; }
            else t2b = fmaxf(t2b, v1);
        }
        if ((lane & 3) == 0) {
            int rA = block_m + warp_m + im * 16 + (lane >> 2);
            g_part[(size_t)rA * NSEG + seg] = make_float4(t1a, t2a, __int_as_float(i1a), 0.f);
            g_part[(size_t)(rA + 8) * NSEG + seg] = make_float4(t1b, t2b, __int_as_float(i1b), 0.f);
        }
    }
}

// ---------------- merge partials -> index + screen flag list ------------------------
__global__ void merge_kernel(int q) {
    int row = blockIdx.x * blockDim.x + threadIdx.x;
    if (row >= NROWS) return;
    float b1 = -1e30f, b2 = -1e30f;
    int bi = 0;
    const float4* p = &g_part[(size_t)row * NSEG];
    #pragma unroll 8
    for (int s = 0; s < NSEG; s++) {
        float4 v = p[s];
        if (v.x > b1) { b2 = fmaxf(b1, v.y); b1 = v.x; bi = __float_as_int(v.z); }
        else          { b2 = fmaxf(b2, v.x); }
    }
    g_indices[row * NQ + q] = bi;
    if (b1 - b2 < DELTA) {
        int pos = atomicAdd(&g_nflag[q], 1);
        g_flaglist[q * NROWS + pos] = row;
    }
}

// ---------------- stage-1: fp32 batched refine, f32x2-packed row pairs --------------
__global__ void __launch_bounds__(256, 2)
refine32_kernel(const float* __restrict__ cb, int q) {
    __shared__ float2 prs[RB / 2][DIM];   // (row2p, row2p+1) interleaved per dim
    __shared__ float ss1[256], ss2[256];
    __shared__ int   si1[256];
    __shared__ int   rows_s[RB];

    const int tid = threadIdx.x;
    const int nf = g_nflag[q];

    for (int batch = blockIdx.x * RB; batch < nf; batch += gridDim.x * RB) {
        const int nr = min(RB, nf - batch);
        if (tid < RB) {
            int j = min(tid, nr - 1);
            rows_s[tid] = g_flaglist[q * NROWS + batch + j];
        }
        __syncthreads();
        for (int d = tid; d < DIM; d += 256) {
            #pragma unroll
            for (int p = 0; p < RB / 2; p++) {
                prs[p][d] = make_float2(g_residual[(size_t)rows_s[2 * p] * DIM + d],
                                        g_residual[(size_t)rows_s[2 * p + 1] * DIM + d]);
            }
        }
        __syncthreads();

        float b1[RB], b2[RB];
        int bi[RB];
        #pragma unroll
        for (int j = 0; j < RB; j++) { b1[j] = -1e30f; b2[j] = -1e30f; bi[j] = 0; }

        for (int v = tid; v < NV; v += 256) {
            const float4* cv = (const float4*)(cb + (size_t)v * DIM);
            unsigned long long acc2[RB / 2];
            #pragma unroll
            for (int p = 0; p < RB / 2; p++) acc2[p] = 0ULL;
            #pragma unroll 2
            for (int t = 0; t < DIM / 4; t++) {
                float4 c = __ldg(cv + t);
                unsigned long long cx = pack2(c.x, c.x);
                unsigned long long cy = pack2(c.y, c.y);
                unsigned long long cz = pack2(c.z, c.z);
                unsigned long long cw = pack2(c.w, c.w);
                #pragma unroll
                for (int p = 0; p < RB / 2; p++) {
                    const ulonglong2* rp = (const ulonglong2*)&prs[p][4 * t];
                    ulonglong2 rA = rp[0];   // dims 4t, 4t+1
                    ulonglong2 rB = rp[1];   // dims 4t+2, 4t+3
                    fma2(acc2[p], cx, rA.x);
                    fma2(acc2[p], cy, rA.y);
                    fma2(acc2[p], cz, rB.x);
                    fma2(acc2[p], cw, rB.y);
                }
            }
            float nrm = g_norms[q * NV + v];
            #pragma unroll
            for (int p = 0; p < RB / 2; p++) {
                float2 dots = unpack2(acc2[p]);
                float s0 = fmaf(2.f, dots.x, -nrm);
                float s1 = fmaf(2.f, dots.y, -nrm);
                int j0 = 2 * p, j1 = 2 * p + 1;
                if (s0 > b1[j0]) { b2[j0] = b1[j0]; b1[j0] = s0; bi[j0] = v; }
                else if (s0 > b2[j0]) b2[j0] = s0;
                if (s1 > b1[j1]) { b2[j1] = b1[j1]; b1[j1] = s1; bi[j1] = v; }
                else if (s1 > b2[j1]) b2[j1] = s1;
            }
        }

        for (int j = 0; j < nr; j++) {
            ss1[tid] = b1[j]; ss2[tid] = b2[j]; si1[tid] = bi[j];
            __syncthreads();
            for (int o = 128; o; o >>= 1) {
                if (tid < o) {
                    float o1 = ss1[tid + o], o2 = ss2[tid + o];
                    int   oi = si1[tid + o];
                    if (o1 > ss1[tid] || (o1 == ss1[tid] && oi < si1[tid])) {
                        ss2[tid] = fmaxf(ss1[tid], o2);
                        ss1[tid] = o1; si1[tid] = oi;
                    } else {
                        ss2[tid] = fmaxf(ss2[tid], o1);
                    }
                }
                __syncthreads();
            }
            if (tid == 0) {
                int row = rows_s[j];
                g_indices[row * NQ + q] = si1[0];
                if (ss1[0] - ss2[0] < TAU2) {
                    int pos = atomicAdd(&g_nflag2[q], 1);
                    if (pos < MAXF2) g_flag2[q * MAXF2 + pos] = row;
                }
            }
            __syncthreads();
        }
    }
}

// ---------------- stage-2a: fp64 per (row, 256-codeword chunk) -----------------------
__global__ void __launch_bounds__(256, 1)
refine64_chunk_kernel(const float* __restrict__ cb, int q) {
    __shared__ float  rsm[DIM];
    __shared__ double sred[256];
    __shared__ int    ired[256];

    const int tid = threadIdx.x;
    int nf2 = g_nflag2[q];
    if (nf2 > MAXF2) nf2 = MAXF2;
    const int nwork = nf2 * 16;

    for (int w = blockIdx.x; w < nwork; w += gridDim.x) {
        const int slot = w >> 4;
        const int chunk = w & 15;
        const int row = g_flag2[q * MAXF2 + slot];
        for (int d = tid; d < DIM; d += 256) rsm[d] = g_residual[(size_t)row * DIM + d];
        __syncthreads();

        const int v = chunk * 256 + tid;
        const float4* cv = (const float4*)(cb + (size_t)v * DIM);
        double a0 = 0, a1 = 0, a2 = 0, a3 = 0, a4 = 0, a5 = 0, a6 = 0, a7 = 0;
        #pragma unroll 4
        for (int t = 0; t < DIM / 4; t += 2) {
            float4 c0 = __ldg(cv + t);
            float4 c1 = __ldg(cv + t + 1);
            const float4 r0 = *(const float4*)&rsm[4 * t];
            const float4 r1 = *(const float4*)&rsm[4 * t + 4];
            a0 = fma((double)r0.x, (double)c0.x, a0);
            a1 = fma((double)r0.y, (double)c0.y, a1);
            a2 = fma((double)r0.z, (double)c0.z, a2);
            a3 = fma((double)r0.w, (double)c0.w, a3);
            a4 = fma((double)r1.x, (double)c1.x, a4);
            a5 = fma((double)r1.y, (double)c1.y, a5);
            a6 = fma((double)r1.z, (double)c1.z, a6);
            a7 = fma((double)r1.w, (double)c1.w, a7);
        }
        double dot = ((a0 + a1) + (a2 + a3)) + ((a4 + a5) + (a6 + a7));
        sred[tid] = 2.0 * dot - g_norms64[q * NV + v];
        ired[tid] = v;
        __syncthreads();
        for (int o = 128; o; o >>= 1) {
            if (tid < o) {
                double so = sred[tid + o]; int vo = ired[tid + o];
                if (so > sred[tid] || (so == sred[tid] && vo < ired[tid])) {
                    sred[tid] = so; ired[tid] = vo;
                }
            }
            __syncthreads();
        }
        if (tid == 0) { g_p2s[slot * 16 + chunk] = sred[0]; g_p2i[slot * 16 + chunk] = ired[0]; }
        __syncthreads();
    }
}

// ---------------- stage-2b: reduce chunk winners -> final index ----------------------
__global__ void refine64_reduce_kernel(int q) {
    int slot = blockIdx.x * blockDim.x + threadIdx.x;
    int nf2 = g_nflag2[q];
    if (nf2 > MAXF2) nf2 = MAXF2;
    if (slot >= nf2) return;
    double b = -1e300;
    int bi = 0;
    #pragma unroll
    for (int c = 0; c < 16; c++) {
        double s = g_p2s[slot * 16 + c];
        int i = g_p2i[slot * 16 + c];
        if (s > b || (s == b && i < bi)) { b = s; bi = i; }
    }
    const int row = g_flag2[q * MAXF2 + slot];
    g_indices[row * NQ + q] = bi;
}

// ---------------- gather + residual/quantized update (+ fp16 hi of residual) --------
__global__ void update_kernel(const float* __restrict__ cb, int q) {
    int gid = blockIdx.x * blockDim.x + threadIdx.x;
    const int PR = DIM / 4;
    int row = gid / PR;
    if (row >= NROWS) return;
    int c = (gid - row * PR) << 2;
    int idx = __ldg(&g_indices[row * NQ + q]);
    const float4 cw = *(const float4*)(cb + (size_t)idx * DIM + c);
    size_t off = (size_t)row * DIM + c;
    float4 r = *(float4*)(g_residual + off);
    float4 z = *(float4*)(g_quantized + off);
    r.x -= cw.x; r.y -= cw.y; r.z -= cw.z; r.w -= cw.w;
    z.x += cw.x; z.y += cw.y; z.z += cw.z; z.w += cw.w;
    *(float4*)(g_residual + off) = r;
    *(float4*)(g_quantized + off) = z;
    store_hi4(g_Ahi + (size_t)row * DIM, c, r);
}

// ---------------- out = x + (quantized - x) -----------------------------------------
__global__ void finalize_kernel(const float* __restrict__ x, float* __restrict__ out) {
    size_t i = (size_t)blockIdx.x * blockDim.x + threadIdx.x;
    if (i >= (size_t)NROWS * DIM / 4) return;
    float4 xv = ((const float4*)x)[i];
    float4 qv = ((const float4*)g_quantized)[i];
    float4 o;
    o.x = xv.x + (qv.x - xv.x);
    o.y = xv.y + (qv.y - xv.y);
    o.z = xv.z + (qv.z - xv.z);
    o.w = xv.w + (qv.w - xv.w);
    ((float4*)out)[i] = o;
}

__global__ void idxout_kernel(float* __restrict__ out) {
    int i = blockIdx.x * blockDim.x + threadIdx.x;
    if (i < NROWS * NQ) out[i] = (float)g_indices[i];
}

extern "C" void kernel_launch(void* const* d_in, const int* in_sizes, int n_in,
                              void* d_out, int out_size) {
    const float* x  = (const float*)d_in[0];
    const float* cb = (const float*)d_in[1];
    float* out = (float*)d_out;

    cudaFuncSetAttribute(score_gemm_kernel,
                         cudaFuncAttributeMaxDynamicSharedMemorySize, SMEM_DYN);

    norms_kernel<<<(NQ * NV) / 8, 256>>>(cb);
    init_kernel<<<(NROWS * DIM / 4 + 255) / 256, 256>>>(x);
    convB_kernel<<<(NQ * NV * (DIM / 4) + 255) / 256, 256>>>(cb);

    for (int q = 0; q < NQ; q++) {
        const float* cbq = cb + (size_t)q * NV * DIM;
        score_gemm_kernel<<<MT2 * NT2, 256, SMEM_DYN>>>(q);
        merge_kernel<<<(NROWS + 255) / 256, 256>>>(q);
        refine32_kernel<<<448, 256>>>(cbq, q);
        refine64_chunk_kernel<<<592, 256>>>(cbq, q);
        refine64_reduce_kernel<<<(MAXF2 + 255) / 256, 256>>>(q);
        update_kernel<<<(NROWS * (DIM / 4) + 255) / 256, 256>>>(cbq, q);
    }

    finalize_kernel<<<(NROWS * DIM / 4 + 255) / 256, 256>>>(x, out);

    if (out_size >= NROWS * DIM + NROWS * NQ) {
        idxout_kernel<<<(NROWS * NQ + 255) / 256, 256>>>(out + (size_t)NROWS * DIM);
    }
}

// round 11
// speedup vs baseline: 10.1822x; 1.5844x over previous
#include <cuda_runtime.h>
#include <cuda_fp16.h>
#include <cstdint>

#define NROWS 32768
#define DIM   768
#define NQ    4
#define NV    4096
#define DELTA 0.25f      // screen flag threshold (~8 sigma of fp16-GEMM pairwise err)
#define TAU2  2e-3f      // rescore -> fp64 threshold (~20 sigma of 3-term GEMM err)
#define MAXF2 4096       // fp64 slot cap
#define MAXRF 4096       // rescore row capacity (32 m-tiles)

#define GBM 128
#define GBN 128
#define KTOT 768
#define BK   64
#define NSTG (KTOT / BK)   // 12 (screen)
#define NSTG2 36           // rescore: 3*768/64
#define NBUF 3
#define NT2  (NV / GBN)    // 32
#define MT2  (NROWS / GBM) // 256
#define SROW  72
#define SROWB 144
#define BUFSZ (128 * SROWB)
#define SMEM_DYN (NBUF * 2 * BUFSZ)
#define NSEG 128

// ---------------- scratch ---------------------------------------------------------
__device__ float  g_residual[(size_t)NROWS * DIM];
__device__ float  g_quantized[(size_t)NROWS * DIM];
__device__ float  g_norms[NQ * NV];
__device__ double g_norms64[NQ * NV];
__device__ int    g_indices[NROWS * NQ];
__device__ int    g_nflag[NQ];
__device__ int    g_flaglist[NQ * NROWS];
__device__ int    g_nflag2[NQ];
__device__ int    g_flag2[NQ * MAXF2];
__device__ double g_p2s[MAXF2 * 16];
__device__ int    g_p2i[MAXF2 * 16];
__device__ __align__(256) __half g_Ahi[(size_t)NROWS * DIM];
__device__ __align__(256) __half g_Alo[(size_t)NROWS * DIM];
__device__ __align__(256) __half g_Bhi[(size_t)NQ * NV * DIM];
__device__ __align__(256) __half g_Blo[(size_t)NQ * NV * DIM];
__device__ float4 g_part[(size_t)NROWS * NSEG];   // screen partials; reused by rescore

// ---------------- PTX helpers ------------------------------------------------------
__device__ __forceinline__ uint32_t smem_u32(const void* p) {
    uint32_t a;
    asm("{ .reg .u64 t; cvta.to.shared.u64 t, %1; cvt.u32.u64 %0, t; }" : "=r"(a) : "l"(p));
    return a;
}
__device__ __forceinline__ void cp16(uint32_t s, const void* g) {
    asm volatile("cp.async.cg.shared.global [%0], [%1], 16;" :: "r"(s), "l"(g));
}
__device__ __forceinline__ void cp_commit() { asm volatile("cp.async.commit_group;"); }
template <int N>
__device__ __forceinline__ void cp_wait() { asm volatile("cp.async.wait_group %0;" :: "n"(N) : "memory"); }

__device__ __forceinline__ void ldm_x4(uint32_t* r, uint32_t a) {
    asm volatile("ldmatrix.sync.aligned.m8n8.x4.shared.b16 {%0,%1,%2,%3}, [%4];"
                 : "=r"(r[0]), "=r"(r[1]), "=r"(r[2]), "=r"(r[3]) : "r"(a));
}
__device__ __forceinline__ void ldm_x2(uint32_t* r, uint32_t a) {
    asm volatile("ldmatrix.sync.aligned.m8n8.x2.shared.b16 {%0,%1}, [%2];"
                 : "=r"(r[0]), "=r"(r[1]) : "r"(a));
}
__device__ __forceinline__ void mma16816(float* d, const uint32_t* a, const uint32_t* b) {
    asm volatile("mma.sync.aligned.m16n8k16.row.col.f32.f16.f16.f32 "
                 "{%0,%1,%2,%3}, {%4,%5,%6,%7}, {%8,%9}, {%0,%1,%2,%3};"
                 : "+f"(d[0]), "+f"(d[1]), "+f"(d[2]), "+f"(d[3])
                 : "r"(a[0]), "r"(a[1]), "r"(a[2]), "r"(a[3]), "r"(b[0]), "r"(b[1]));
}

__device__ __forceinline__ void store_hilo4(__half* hb, __half* lb, int c, float4 r) {
    __half h0 = __float2half_rn(r.x), h1 = __float2half_rn(r.y);
    __half h2 = __float2half_rn(r.z), h3 = __float2half_rn(r.w);
    *(__half2*)(hb + c)     = __halves2half2(h0, h1);
    *(__half2*)(hb + c + 2) = __halves2half2(h2, h3);
    *(__half2*)(lb + c)     = __halves2half2(__float2half_rn(r.x - __half2float(h0)),
                                             __float2half_rn(r.y - __half2float(h1)));
    *(__half2*)(lb + c + 2) = __halves2half2(__float2half_rn(r.z - __half2float(h2)),
                                             __float2half_rn(r.w - __half2float(h3)));
}

// ---------------- ||c||^2 per codeword (fp64 + fp32 copy) --------------------------
__global__ void norms_kernel(const float* __restrict__ cb) {
    int w = (blockIdx.x * blockDim.x + threadIdx.x) >> 5;
    int lane = threadIdx.x & 31;
    if (w >= NQ * NV) return;
    const float* c = cb + (size_t)w * DIM;
    double s = 0.0;
    #pragma unroll 4
    for (int d = lane; d < DIM; d += 32) {
        double v = (double)__ldg(c + d);
        s = fma(v, v, s);
    }
    #pragma unroll
    for (int o = 16; o; o >>= 1) s += __shfl_xor_sync(0xffffffffu, s, o);
    if (lane == 0) { g_norms64[w] = s; g_norms[w] = (float)s; }
}

// ---------------- residual = x (+ fp16 hi/lo), quantized = 0, flags = 0 -------------
__global__ void init_kernel(const float* __restrict__ x) {
    size_t i = (size_t)blockIdx.x * blockDim.x + threadIdx.x;
    if (i < NQ) { g_nflag[i] = 0; g_nflag2[i] = 0; }
    if (i >= (size_t)NROWS * DIM / 4) return;
    float4 v = ((const float4*)x)[i];
    ((float4*)g_residual)[i] = v;
    ((float4*)g_quantized)[i] = make_float4(0.f, 0.f, 0.f, 0.f);
    int row = (int)(i / (DIM / 4));
    int c = (int)(i - (size_t)row * (DIM / 4)) * 4;
    store_hilo4(g_Ahi + (size_t)row * DIM, g_Alo + (size_t)row * DIM, c, v);
}

// ---------------- codebooks -> fp16 hi/lo (once) ------------------------------------
__global__ void convB_kernel(const float* __restrict__ cb) {
    int i = blockIdx.x * blockDim.x + threadIdx.x;
    if (i >= NQ * NV * (DIM / 4)) return;
    float4 v = *(const float4*)(cb + (size_t)i * 4);
    store_hilo4(g_Bhi, g_Blo, i * 4, v);
}

// ---------------- mma.sync screen GEMM + per-row/segment top-2 ----------------------
__global__ void __launch_bounds__(256, 2)
score_gemm_kernel(int q) {
    extern __shared__ char dyn[];
    __shared__ float snorm[GBN];
    const uint32_t sbase = smem_u32(dyn);

    const int tid = threadIdx.x;
    const int wid = tid >> 5;
    const int lane = tid & 31;
    const int nt = blockIdx.x & (NT2 - 1);
    const int mt = blockIdx.x >> 5;
    const int block_m = mt * GBM;
    const int ncol0 = nt * GBN;
    const int warp_m = (wid >> 2) * 64;
    const int warp_n = (wid & 3) * 32;

    if (tid < GBN) snorm[tid] = g_norms[q * NV + ncol0 + tid];

    const char* Abase = (const char*)g_Ahi + (size_t)block_m * DIM * 2;
    const char* Bbase = (const char*)(g_Bhi + (size_t)q * NV * DIM)
                        + (size_t)ncol0 * DIM * 2;

    auto issue = [&](int s) {
        const int b = s % NBUF;
        const int k0 = s * BK;
        const uint32_t dA = sbase + b * (2 * BUFSZ);
        const uint32_t dB = dA + BUFSZ;
        const char* Ab = Abase + (size_t)k0 * 2;
        const char* Bb = Bbase + (size_t)k0 * 2;
        #pragma unroll
        for (int i = 0; i < 4; i++) {
            int ch = tid + i * 256;
            int r = ch >> 3, c16 = (ch & 7) * 16;
            cp16(dA + r * SROWB + c16, Ab + (size_t)r * (DIM * 2) + c16);
        }
        #pragma unroll
        for (int i = 0; i < 4; i++) {
            int ch = tid + i * 256;
            int r = ch >> 3, c16 = (ch & 7) * 16;
            cp16(dB + r * SROWB + c16, Bb + (size_t)r * (DIM * 2) + c16);
        }
        cp_commit();
    };

    float acc[4][4][4];
    #pragma unroll
    for (int im = 0; im < 4; im++)
        #pragma unroll
        for (int in = 0; in < 4; in++)
            #pragma unroll
            for (int e = 0; e < 4; e++) acc[im][in][e] = 0.f;

    issue(0);
    issue(1);

    const int arow = lane & 15;
    const int acolh = (lane >> 4) * 8;
    const int brow = lane & 7;
    const int bcolh = ((lane >> 3) & 1) * 8;

    #pragma unroll
    for (int s = 0; s < NSTG; ++s) {
        if (s < NSTG - 1) cp_wait<1>(); else cp_wait<0>();
        __syncthreads();
        if (s + 2 < NSTG) issue(s + 2);

        const uint32_t aB = sbase + (s % NBUF) * (2 * BUFSZ);
        const uint32_t bB = aB + BUFSZ;
        #pragma unroll
        for (int kk = 0; kk < 4; kk++) {
            const int k0 = kk * 16;
            uint32_t afr[4][4];
            #pragma unroll
            for (int im = 0; im < 4; im++) {
                uint32_t addr = aB + (warp_m + im * 16 + arow) * SROWB + (k0 + acolh) * 2;
                ldm_x4(afr[im], addr);
            }
            #pragma unroll
            for (int in = 0; in < 4; in++) {
                uint32_t bfr[2];
                uint32_t addr = bB + (warp_n + in * 8 + brow) * SROWB + (k0 + bcolh) * 2;
                ldm_x2(bfr, addr);
                #pragma unroll
                for (int im = 0; im < 4; im++) mma16816(acc[im][in], afr[im], bfr);
            }
        }
    }

    const int seg = nt * 4 + (wid & 3);
    #pragma unroll
    for (int im = 0; im < 4; im++) {
        float t1a = -1e30f, t2a = -1e30f, t1b = -1e30f, t2b = -1e30f;
        int i1a = 0, i1b = 0;
        #pragma unroll
        for (int in = 0; in < 4; in++) {
            int c = warp_n + in * 8 + (lane & 3) * 2;
            float n0 = snorm[c], n1 = snorm[c + 1];
            float sa0 = fmaf(2.f, acc[im][in][0], -n0);
            float sa1 = fmaf(2.f, acc[im][in][1], -n1);
            float sb0 = fmaf(2.f, acc[im][in][2], -n0);
            float sb1 = fmaf(2.f, acc[im][in][3], -n1);
            int gc = ncol0 + c;
            if (sa0 > t1a) { t2a = t1a; t1a = sa0; i1a = gc; } else if (sa0 > t2a) t2a = sa0;
            if (sa1 > t1a) { t2a = t1a; t1a = sa1; i1a = gc + 1; } else if (sa1 > t2a) t2a = sa1;
            if (sb0 > t1b) { t2b = t1b; t1b = sb0; i1b = gc; } else if (sb0 > t2b) t2b = sb0;
            if (sb1 > t1b) { t2b = t1b; t1b = sb1; i1b = gc + 1; } else if (sb1 > t2b) t2b = sb1;
        }
        #pragma unroll
        for (int o = 1; o < 4; o <<= 1) {
            float u1 = __shfl_xor_sync(0xffffffffu, t1a, o);
            float u2 = __shfl_xor_sync(0xffffffffu, t2a, o);
            int   ui = __shfl_xor_sync(0xffffffffu, i1a, o);
            if (u1 > t1a || (u1 == t1a && ui < i1a)) { t2a = fmaxf(t1a, u2); t1a = u1; i1a = ui; }
            else t2a = fmaxf(t2a, u1);
            float v1 = __shfl_xor_sync(0xffffffffu, t1b, o);
            float v2 = __shfl_xor_sync(0xffffffffu, t2b, o);
            int   vi = __shfl_xor_sync(0xffffffffu, i1b, o);
            if (v1 > t1b || (v1 == t1b && vi < i1b)) { t2b = fmaxf(t1b, v2); t1b = v1; i1b = vi; }
            else t2b = fmaxf(t2b, v1);
        }
        if ((lane & 3) == 0) {
            int rA = block_m + warp_m + im * 16 + (lane >> 2);
            g_part[(size_t)rA * NSEG + seg] = make_float4(t1a, t2a, __int_as_float(i1a), 0.f);
            g_part[(size_t)(rA + 8) * NSEG + seg] = make_float4(t1b, t2b, __int_as_float(i1b), 0.f);
        }
    }
}

// ---------------- merge partials -> index + screen flag list ------------------------
__global__ void merge_kernel(int q) {
    int row = blockIdx.x * blockDim.x + threadIdx.x;
    if (row >= NROWS) return;
    float b1 = -1e30f, b2 = -1e30f;
    int bi = 0;
    const float4* p = &g_part[(size_t)row * NSEG];
    #pragma unroll 8
    for (int s = 0; s < NSEG; s++) {
        float4 v = p[s];
        if (v.x > b1) { b2 = fmaxf(b1, v.y); b1 = v.x; bi = __float_as_int(v.z); }
        else          { b2 = fmaxf(b2, v.x); }
    }
    g_indices[row * NQ + q] = bi;
    if (b1 - b2 < DELTA) {
        int pos = atomicAdd(&g_nflag[q], 1);
        g_flaglist[q * NROWS + pos] = row;
    }
}

// ---------------- rescore: 3-term split GEMM on flagged rows (K=2304) ---------------
// grid 32 m-tiles x 32 nt; blocks beyond ceil(nf/128) m-tiles exit. A rows gathered
// via flaglist (indices staged in smem). Partials keyed by SLOT (flaglist position).
__global__ void __launch_bounds__(256, 2)
rescore_gemm_kernel(int q) {
    extern __shared__ char dyn[];
    __shared__ float snorm[GBN];
    __shared__ int   srows[GBM];
    const uint32_t sbase = smem_u32(dyn);

    int nf = g_nflag[q];
    if (nf > MAXRF) nf = MAXRF;
    const int nt = blockIdx.x & (NT2 - 1);
    const int mt = blockIdx.x >> 5;
    if (mt * GBM >= nf) return;

    const int tid = threadIdx.x;
    const int wid = tid >> 5;
    const int lane = tid & 31;
    const int ncol0 = nt * GBN;
    const int warp_m = (wid >> 2) * 64;
    const int warp_n = (wid & 3) * 32;

    if (tid < GBN) snorm[tid] = g_norms[q * NV + ncol0 + tid];
    if (tid < GBM) {
        int slot = mt * GBM + tid;
        srows[tid] = g_flaglist[q * NROWS + min(slot, nf - 1)];
    }
    __syncthreads();

    auto issue = [&](int s) {
        const int b = s % NBUF;
        const int seg3 = s / 12;              // 0: hi*hi  1: hi*lo  2: lo*hi
        const int k0 = (s - seg3 * 12) * BK;  // column within 768
        const __half* Asrc = (seg3 < 2) ? g_Ahi : g_Alo;
        const __half* Bsrc = (seg3 == 1) ? g_Blo : g_Bhi;
        const char* Bb = (const char*)(Bsrc + (size_t)q * NV * DIM)
                         + ((size_t)ncol0 * DIM + k0) * 2;
        const uint32_t dA = sbase + b * (2 * BUFSZ);
        const uint32_t dB = dA + BUFSZ;
        #pragma unroll
        for (int i = 0; i < 4; i++) {
            int ch = tid + i * 256;
            int r = ch >> 3, c16 = (ch & 7) * 16;
            const char* Ab = (const char*)(Asrc + (size_t)srows[r] * DIM + k0);
            cp16(dA + r * SROWB + c16, Ab + c16);
        }
        #pragma unroll
        for (int i = 0; i < 4; i++) {
            int ch = tid + i * 256;
            int r = ch >> 3, c16 = (ch & 7) * 16;
            cp16(dB + r * SROWB + c16, Bb + (size_t)r * (DIM * 2) + c16);
        }
        cp_commit();
    };

    float acc[4][4][4];
    #pragma unroll
    for (int im = 0; im < 4; im++)
        #pragma unroll
        for (int in = 0; in < 4; in++)
            #pragma unroll
            for (int e = 0; e < 4; e++) acc[im][in][e] = 0.f;

    issue(0);
    issue(1);

    const int arow = lane & 15;
    const int acolh = (lane >> 4) * 8;
    const int brow = lane & 7;
    const int bcolh = ((lane >> 3) & 1) * 8;

    #pragma unroll 1
    for (int s = 0; s < NSTG2; ++s) {
        if (s < NSTG2 - 1) cp_wait<1>(); else cp_wait<0>();
        __syncthreads();
        if (s + 2 < NSTG2) issue(s + 2);

        const uint32_t aB = sbase + (s % NBUF) * (2 * BUFSZ);
        const uint32_t bB = aB + BUFSZ;
        #pragma unroll
        for (int kk = 0; kk < 4; kk++) {
            const int k0 = kk * 16;
            uint32_t afr[4][4];
            #pragma unroll
            for (int im = 0; im < 4; im++) {
                uint32_t addr = aB + (warp_m + im * 16 + arow) * SROWB + (k0 + acolh) * 2;
                ldm_x4(afr[im], addr);
            }
            #pragma unroll
            for (int in = 0; in < 4; in++) {
                uint32_t bfr[2];
                uint32_t addr = bB + (warp_n + in * 8 + brow) * SROWB + (k0 + bcolh) * 2;
                ldm_x2(bfr, addr);
                #pragma unroll
                for (int im = 0; im < 4; im++) mma16816(acc[im][in], afr[im], bfr);
            }
        }
    }

    // per-SLOT top-2 partials into g_part[slot]
    const int seg = nt * 4 + (wid & 3);
    #pragma unroll
    for (int im = 0; im < 4; im++) {
        float t1a = -1e30f, t2a = -1e30f, t1b = -1e30f, t2b = -1e30f;
        int i1a = 0, i1b = 0;
        #pragma unroll
        for (int in = 0; in < 4; in++) {
            int c = warp_n + in * 8 + (lane & 3) * 2;
            float n0 = snorm[c], n1 = snorm[c + 1];
            float sa0 = fmaf(2.f, acc[im][in][0], -n0);
            float sa1 = fmaf(2.f, acc[im][in][1], -n1);
            float sb0 = fmaf(2.f, acc[im][in][2], -n0);
            float sb1 = fmaf(2.f, acc[im][in][3], -n1);
            int gc = ncol0 + c;
            if (sa0 > t1a) { t2a = t1a; t1a = sa0; i1a = gc; } else if (sa0 > t2a) t2a = sa0;
            if (sa1 > t1a) { t2a = t1a; t1a = sa1; i1a = gc + 1; } else if (sa1 > t2a) t2a = sa1;
            if (sb0 > t1b) { t2b = t1b; t1b = sb0; i1b = gc; } else if (sb0 > t2b) t2b = sb0;
            if (sb1 > t1b) { t2b = t1b; t1b = sb1; i1b = gc + 1; } else if (sb1 > t2b) t2b = sb1;
        }
        #pragma unroll
        for (int o = 1; o < 4; o <<= 1) {
            float u1 = __shfl_xor_sync(0xffffffffu, t1a, o);
            float u2 = __shfl_xor_sync(0xffffffffu, t2a, o);
            int   ui = __shfl_xor_sync(0xffffffffu, i1a, o);
            if (u1 > t1a || (u1 == t1a && ui < i1a)) { t2a = fmaxf(t1a, u2); t1a = u1; i1a = ui; }
            else t2a = fmaxf(t2a, u1);
            float v1 = __shfl_xor_sync(0xffffffffu, t1b, o);
            float v2 = __shfl_xor_sync(0xffffffffu, t2b, o);
            int   vi = __shfl_xor_sync(0xffffffffu, i1b, o);
            if (v1 > t1b || (v1 == t1b && vi < i1b)) { t2b = fmaxf(t1b, v2); t1b = v1; i1b = vi; }
            else t2b = fmaxf(t2b, v1);
        }
        if ((lane & 3) == 0) {
            int slotA = mt * GBM + warp_m + im * 16 + (lane >> 2);
            g_part[(size_t)slotA * NSEG + seg] = make_float4(t1a, t2a, __int_as_float(i1a), 0.f);
            g_part[(size_t)(slotA + 8) * NSEG + seg] = make_float4(t1b, t2b, __int_as_float(i1b), 0.f);
        }
    }
}

// ---------------- merge rescore partials -> final index (+ fp64 flags) --------------
__global__ void merge2_kernel(int q) {
    int slot = blockIdx.x * blockDim.x + threadIdx.x;
    int nf = g_nflag[q];
    if (nf > MAXRF) nf = MAXRF;
    if (slot >= nf) return;
    float b1 = -1e30f, b2 = -1e30f;
    int bi = 0;
    const float4* p = &g_part[(size_t)slot * NSEG];
    #pragma unroll 8
    for (int s = 0; s < NSEG; s++) {
        float4 v = p[s];
        if (v.x > b1) { b2 = fmaxf(b1, v.y); b1 = v.x; bi = __float_as_int(v.z); }
        else          { b2 = fmaxf(b2, v.x); }
    }
    const int row = g_flaglist[q * NROWS + slot];
    g_indices[row * NQ + q] = bi;
    if (b1 - b2 < TAU2) {
        int pos = atomicAdd(&g_nflag2[q], 1);
        if (pos < MAXF2) g_flag2[q * MAXF2 + pos] = row;
    }
}

// ---------------- fp64 per (row, 256-codeword chunk) --------------------------------
__global__ void __launch_bounds__(256, 1)
refine64_chunk_kernel(const float* __restrict__ cb, int q) {
    __shared__ float  rsm[DIM];
    __shared__ double sred[256];
    __shared__ int    ired[256];

    const int tid = threadIdx.x;
    int nf2 = g_nflag2[q];
    if (nf2 > MAXF2) nf2 = MAXF2;
    const int nwork = nf2 * 16;

    for (int w = blockIdx.x; w < nwork; w += gridDim.x) {
        const int slot = w >> 4;
        const int chunk = w & 15;
        const int row = g_flag2[q * MAXF2 + slot];
        for (int d = tid; d < DIM; d += 256) rsm[d] = g_residual[(size_t)row * DIM + d];
        __syncthreads();

        const int v = chunk * 256 + tid;
        const float4* cv = (const float4*)(cb + (size_t)v * DIM);
        double a0 = 0, a1 = 0, a2 = 0, a3 = 0, a4 = 0, a5 = 0, a6 = 0, a7 = 0;
        #pragma unroll 4
        for (int t = 0; t < DIM / 4; t += 2) {
            float4 c0 = __ldg(cv + t);
            float4 c1 = __ldg(cv + t + 1);
            const float4 r0 = *(const float4*)&rsm[4 * t];
            const float4 r1 = *(const float4*)&rsm[4 * t + 4];
            a0 = fma((double)r0.x, (double)c0.x, a0);
            a1 = fma((double)r0.y, (double)c0.y, a1);
            a2 = fma((double)r0.z, (double)c0.z, a2);
            a3 = fma((double)r0.w, (double)c0.w, a3);
            a4 = fma((double)r1.x, (double)c1.x, a4);
            a5 = fma((double)r1.y, (double)c1.y, a5);
            a6 = fma((double)r1.z, (double)c1.z, a6);
            a7 = fma((double)r1.w, (double)c1.w, a7);
        }
        double dot = ((a0 + a1) + (a2 + a3)) + ((a4 + a5) + (a6 + a7));
        sred[tid] = 2.0 * dot - g_norms64[q * NV + v];
        ired[tid] = v;
        __syncthreads();
        for (int o = 128; o; o >>= 1) {
            if (tid < o) {
                double so = sred[tid + o]; int vo = ired[tid + o];
                if (so > sred[tid] || (so == sred[tid] && vo < ired[tid])) {
                    sred[tid] = so; ired[tid] = vo;
                }
            }
            __syncthreads();
        }
        if (tid == 0) { g_p2s[slot * 16 + chunk] = sred[0]; g_p2i[slot * 16 + chunk] = ired[0]; }
        __syncthreads();
    }
}

// ---------------- reduce fp64 chunk winners -> final index ---------------------------
__global__ void refine64_reduce_kernel(int q) {
    int slot = blockIdx.x * blockDim.x + threadIdx.x;
    int nf2 = g_nflag2[q];
    if (nf2 > MAXF2) nf2 = MAXF2;
    if (slot >= nf2) return;
    double b = -1e300;
    int bi = 0;
    #pragma unroll
    for (int c = 0; c < 16; c++) {
        double s = g_p2s[slot * 16 + c];
        int i = g_p2i[slot * 16 + c];
        if (s > b || (s == b && i < bi)) { b = s; bi = i; }
    }
    const int row = g_flag2[q * MAXF2 + slot];
    g_indices[row * NQ + q] = bi;
}

// ---------------- gather + residual/quantized update (+ fp16 hi/lo) -----------------
__global__ void update_kernel(const float* __restrict__ cb, int q) {
    int gid = blockIdx.x * blockDim.x + threadIdx.x;
    const int PR = DIM / 4;
    int row = gid / PR;
    if (row >= NROWS) return;
    int c = (gid - row * PR) << 2;
    int idx = __ldg(&g_indices[row * NQ + q]);
    const float4 cw = *(const float4*)(cb + (size_t)idx * DIM + c);
    size_t off = (size_t)row * DIM + c;
    float4 r = *(float4*)(g_residual + off);
    float4 z = *(float4*)(g_quantized + off);
    r.x -= cw.x; r.y -= cw.y; r.z -= cw.z; r.w -= cw.w;
    z.x += cw.x; z.y += cw.y; z.z += cw.z; z.w += cw.w;
    *(float4*)(g_residual + off) = r;
    *(float4*)(g_quantized + off) = z;
    store_hilo4(g_Ahi + (size_t)row * DIM, g_Alo + (size_t)row * DIM, c, r);
}

// ---------------- out = x + (quantized - x) -----------------------------------------
__global__ void finalize_kernel(const float* __restrict__ x, float* __restrict__ out) {
    size_t i = (size_t)blockIdx.x * blockDim.x + threadIdx.x;
    if (i >= (size_t)NROWS * DIM / 4) return;
    float4 xv = ((const float4*)x)[i];
    float4 qv = ((const float4*)g_quantized)[i];
    float4 o;
    o.x = xv.x + (qv.x - xv.x);
    o.y = xv.y + (qv.y - xv.y);
    o.z = xv.z + (qv.z - xv.z);
    o.w = xv.w + (qv.w - xv.w);
    ((float4*)out)[i] = o;
}

__global__ void idxout_kernel(float* __restrict__ out) {
    int i = blockIdx.x * blockDim.x + threadIdx.x;
    if (i < NROWS * NQ) out[i] = (float)g_indices[i];
}

extern "C" void kernel_launch(void* const* d_in, const int* in_sizes, int n_in,
                              void* d_out, int out_size) {
    const float* x  = (const float*)d_in[0];
    const float* cb = (const float*)d_in[1];
    float* out = (float*)d_out;

    cudaFuncSetAttribute(score_gemm_kernel,
                         cudaFuncAttributeMaxDynamicSharedMemorySize, SMEM_DYN);
    cudaFuncSetAttribute(rescore_gemm_kernel,
                         cudaFuncAttributeMaxDynamicSharedMemorySize, SMEM_DYN);

    norms_kernel<<<(NQ * NV) / 8, 256>>>(cb);
    init_kernel<<<(NROWS * DIM / 4 + 255) / 256, 256>>>(x);
    convB_kernel<<<(NQ * NV * (DIM / 4) + 255) / 256, 256>>>(cb);

    for (int q = 0; q < NQ; q++) {
        const float* cbq = cb + (size_t)q * NV * DIM;
        score_gemm_kernel<<<MT2 * NT2, 256, SMEM_DYN>>>(q);
        merge_kernel<<<(NROWS + 255) / 256, 256>>>(q);
        rescore_gemm_kernel<<<(MAXRF / GBM) * NT2, 256, SMEM_DYN>>>(q);
        merge2_kernel<<<(MAXRF + 255) / 256, 256>>>(q);
        refine64_chunk_kernel<<<592, 256>>>(cbq, q);
        refine64_reduce_kernel<<<(MAXF2 + 255) / 256, 256>>>(q);
        update_kernel<<<(NROWS * (DIM / 4) + 255) / 256, 256>>>(cbq, q);
    }

    finalize_kernel<<<(NROWS * DIM / 4 + 255) / 256, 256>>>(x, out);

    if (out_size >= NROWS * DIM + NROWS * NQ) {
        idxout_kernel<<<(NROWS * NQ + 255) / 256, 256>>>(out + (size_t)NROWS * DIM);
    }
}

// round 12
// speedup vs baseline: 10.8043x; 1.0611x over previous
#include <cuda_runtime.h>
#include <cuda_fp16.h>
#include <cstdint>

#define NROWS 32768
#define DIM   768
#define NQ    4
#define NV    4096
#define DELTA 0.20f      // screen flag threshold (~6.5 sigma of fp16-GEMM pairwise err)
#define TAU2  2e-3f      // rescore -> fp64 threshold (~20 sigma of 3-term GEMM err)
#define MAXF2 4096       // fp64 slot cap
#define MAXRF 4096       // rescore row capacity

#define GBM 128
#define GBN 128
#define KTOT 768
#define BK   64
#define NSTG (KTOT / BK)   // 12 (screen)
#define NSTG2 36           // rescore: 3*768/64
#define NBUF 3
#define NT2  (NV / GBN)    // 32
#define MT2  (NROWS / GBM) // 256
#define SROW  72
#define SROWB 144
#define BUFSZ (128 * SROWB)
#define SMEM_DYN (NBUF * 2 * BUFSZ)
#define NSEG 64            // NT2 * 2 n-warp segments of 64 cols
#define NTHR 128           // 4 warps: 2m x 2n, warp tile 64x64

// ---------------- scratch ---------------------------------------------------------
__device__ float  g_residual[(size_t)NROWS * DIM];
__device__ float  g_norms[NQ * NV];
__device__ double g_norms64[NQ * NV];
__device__ int    g_indices[NROWS * NQ];
__device__ int    g_nflag[NQ];
__device__ int    g_flaglist[NQ * NROWS];
__device__ int    g_nflag2[NQ];
__device__ int    g_flag2[NQ * MAXF2];
__device__ double g_p2s[MAXF2 * 16];
__device__ int    g_p2i[MAXF2 * 16];
__device__ __align__(256) __half g_Ahi[(size_t)NROWS * DIM];
__device__ __align__(256) __half g_Alo[(size_t)NROWS * DIM];
__device__ __align__(256) __half g_Bhi[(size_t)NQ * NV * DIM];
__device__ __align__(256) __half g_Blo[(size_t)NQ * NV * DIM];
__device__ float4 g_part[(size_t)NROWS * NSEG];   // screen partials; reused by rescore

// ---------------- PTX helpers ------------------------------------------------------
__device__ __forceinline__ uint32_t smem_u32(const void* p) {
    uint32_t a;
    asm("{ .reg .u64 t; cvta.to.shared.u64 t, %1; cvt.u32.u64 %0, t; }" : "=r"(a) : "l"(p));
    return a;
}
__device__ __forceinline__ void cp16(uint32_t s, const void* g) {
    asm volatile("cp.async.cg.shared.global [%0], [%1], 16;" :: "r"(s), "l"(g));
}
__device__ __forceinline__ void cp_commit() { asm volatile("cp.async.commit_group;"); }
template <int N>
__device__ __forceinline__ void cp_wait() { asm volatile("cp.async.wait_group %0;" :: "n"(N) : "memory"); }

__device__ __forceinline__ void ldm_x4(uint32_t* r, uint32_t a) {
    asm volatile("ldmatrix.sync.aligned.m8n8.x4.shared.b16 {%0,%1,%2,%3}, [%4];"
                 : "=r"(r[0]), "=r"(r[1]), "=r"(r[2]), "=r"(r[3]) : "r"(a));
}
__device__ __forceinline__ void ldm_x2(uint32_t* r, uint32_t a) {
    asm volatile("ldmatrix.sync.aligned.m8n8.x2.shared.b16 {%0,%1}, [%2];"
                 : "=r"(r[0]), "=r"(r[1]) : "r"(a));
}
__device__ __forceinline__ void mma16816(float* d, const uint32_t* a, const uint32_t* b) {
    asm volatile("mma.sync.aligned.m16n8k16.row.col.f32.f16.f16.f32 "
                 "{%0,%1,%2,%3}, {%4,%5,%6,%7}, {%8,%9}, {%0,%1,%2,%3};"
                 : "+f"(d[0]), "+f"(d[1]), "+f"(d[2]), "+f"(d[3])
                 : "r"(a[0]), "r"(a[1]), "r"(a[2]), "r"(a[3]), "r"(b[0]), "r"(b[1]));
}

__device__ __forceinline__ void store_hilo4(__half* hb, __half* lb, int c, float4 r) {
    __half h0 = __float2half_rn(r.x), h1 = __float2half_rn(r.y);
    __half h2 = __float2half_rn(r.z), h3 = __float2half_rn(r.w);
    *(__half2*)(hb + c)     = __halves2half2(h0, h1);
    *(__half2*)(hb + c + 2) = __halves2half2(h2, h3);
    *(__half2*)(lb + c)     = __halves2half2(__float2half_rn(r.x - __half2float(h0)),
                                             __float2half_rn(r.y - __half2float(h1)));
    *(__half2*)(lb + c + 2) = __halves2half2(__float2half_rn(r.z - __half2float(h2)),
                                             __float2half_rn(r.w - __half2float(h3)));
}

// ---------------- ||c||^2 per codeword (fp64 + fp32 copy) --------------------------
__global__ void norms_kernel(const float* __restrict__ cb) {
    int w = (blockIdx.x * blockDim.x + threadIdx.x) >> 5;
    int lane = threadIdx.x & 31;
    if (w >= NQ * NV) return;
    const float* c = cb + (size_t)w * DIM;
    double s = 0.0;
    #pragma unroll 4
    for (int d = lane; d < DIM; d += 32) {
        double v = (double)__ldg(c + d);
        s = fma(v, v, s);
    }
    #pragma unroll
    for (int o = 16; o; o >>= 1) s += __shfl_xor_sync(0xffffffffu, s, o);
    if (lane == 0) { g_norms64[w] = s; g_norms[w] = (float)s; }
}

// ---------------- residual = x (+ fp16 hi/lo), flags = 0 ----------------------------
__global__ void init_kernel(const float* __restrict__ x) {
    size_t i = (size_t)blockIdx.x * blockDim.x + threadIdx.x;
    if (i < NQ) { g_nflag[i] = 0; g_nflag2[i] = 0; }
    if (i >= (size_t)NROWS * DIM / 4) return;
    float4 v = ((const float4*)x)[i];
    ((float4*)g_residual)[i] = v;
    int row = (int)(i / (DIM / 4));
    int c = (int)(i - (size_t)row * (DIM / 4)) * 4;
    store_hilo4(g_Ahi + (size_t)row * DIM, g_Alo + (size_t)row * DIM, c, v);
}

// ---------------- codebooks -> fp16 hi/lo (once) ------------------------------------
__global__ void convB_kernel(const float* __restrict__ cb) {
    int i = blockIdx.x * blockDim.x + threadIdx.x;
    if (i >= NQ * NV * (DIM / 4)) return;
    float4 v = *(const float4*)(cb + (size_t)i * 4);
    store_hilo4(g_Bhi, g_Blo, i * 4, v);
}

// ======== shared tile-compute for 4-warp 128x128 block, warp tile 64x64 =============
// epilogue writes per-slot top-2 into g_part[slotbase + ...]

__device__ __forceinline__ void gemm_epilogue(
    float acc[4][8][4], const float* snorm, int ncol0, int nt,
    int warp_m, int warp_n, int wid, int lane, int slot_base) {
    const int seg = nt * 2 + (wid & 1);
    #pragma unroll
    for (int im = 0; im < 4; im++) {
        float t1a = -1e30f, t2a = -1e30f, t1b = -1e30f, t2b = -1e30f;
        int i1a = 0, i1b = 0;
        #pragma unroll
        for (int in = 0; in < 8; in++) {
            int c = warp_n + in * 8 + (lane & 3) * 2;
            float n0 = snorm[c], n1 = snorm[c + 1];
            float sa0 = fmaf(2.f, acc[im][in][0], -n0);
            float sa1 = fmaf(2.f, acc[im][in][1], -n1);
            float sb0 = fmaf(2.f, acc[im][in][2], -n0);
            float sb1 = fmaf(2.f, acc[im][in][3], -n1);
            int gc = ncol0 + c;
            if (sa0 > t1a) { t2a = t1a; t1a = sa0; i1a = gc; } else if (sa0 > t2a) t2a = sa0;
            if (sa1 > t1a) { t2a = t1a; t1a = sa1; i1a = gc + 1; } else if (sa1 > t2a) t2a = sa1;
            if (sb0 > t1b) { t2b = t1b; t1b = sb0; i1b = gc; } else if (sb0 > t2b) t2b = sb0;
            if (sb1 > t1b) { t2b = t1b; t1b = sb1; i1b = gc + 1; } else if (sb1 > t2b) t2b = sb1;
        }
        #pragma unroll
        for (int o = 1; o < 4; o <<= 1) {
            float u1 = __shfl_xor_sync(0xffffffffu, t1a, o);
            float u2 = __shfl_xor_sync(0xffffffffu, t2a, o);
            int   ui = __shfl_xor_sync(0xffffffffu, i1a, o);
            if (u1 > t1a || (u1 == t1a && ui < i1a)) { t2a = fmaxf(t1a, u2); t1a = u1; i1a = ui; }
            else t2a = fmaxf(t2a, u1);
            float v1 = __shfl_xor_sync(0xffffffffu, t1b, o);
            float v2 = __shfl_xor_sync(0xffffffffu, t2b, o);
            int   vi = __shfl_xor_sync(0xffffffffu, i1b, o);
            if (v1 > t1b || (v1 == t1b && vi < i1b)) { t2b = fmaxf(t1b, v2); t1b = v1; i1b = vi; }
            else t2b = fmaxf(t2b, v1);
        }
        if ((lane & 3) == 0) {
            int rA = slot_base + warp_m + im * 16 + (lane >> 2);
            g_part[(size_t)rA * NSEG + seg] = make_float4(t1a, t2a, __int_as_float(i1a), 0.f);
            g_part[(size_t)(rA + 8) * NSEG + seg] = make_float4(t1b, t2b, __int_as_float(i1b), 0.f);
        }
    }
}

// ---------------- mma.sync screen GEMM (K=768, hi only) ------------------------------
__global__ void __launch_bounds__(NTHR, 2)
score_gemm_kernel(int q) {
    extern __shared__ char dyn[];
    __shared__ float snorm[GBN];
    const uint32_t sbase = smem_u32(dyn);

    const int tid = threadIdx.x;
    const int wid = tid >> 5;
    const int lane = tid & 31;
    const int nt = blockIdx.x & (NT2 - 1);
    const int mt = blockIdx.x >> 5;
    const int block_m = mt * GBM;
    const int ncol0 = nt * GBN;
    const int warp_m = (wid >> 1) * 64;
    const int warp_n = (wid & 1) * 64;

    snorm[tid] = g_norms[q * NV + ncol0 + tid];   // 128 threads cover GBN=128

    const char* Abase = (const char*)g_Ahi + (size_t)block_m * DIM * 2;
    const char* Bbase = (const char*)(g_Bhi + (size_t)q * NV * DIM)
                        + (size_t)ncol0 * DIM * 2;

    auto issue = [&](int s) {
        const int b = s % NBUF;
        const int k0 = s * BK;
        const uint32_t dA = sbase + b * (2 * BUFSZ);
        const uint32_t dB = dA + BUFSZ;
        const char* Ab = Abase + (size_t)k0 * 2;
        const char* Bb = Bbase + (size_t)k0 * 2;
        #pragma unroll
        for (int i = 0; i < 8; i++) {
            int ch = tid + i * NTHR;
            int r = ch >> 3, c16 = (ch & 7) * 16;
            cp16(dA + r * SROWB + c16, Ab + (size_t)r * (DIM * 2) + c16);
        }
        #pragma unroll
        for (int i = 0; i < 8; i++) {
            int ch = tid + i * NTHR;
            int r = ch >> 3, c16 = (ch & 7) * 16;
            cp16(dB + r * SROWB + c16, Bb + (size_t)r * (DIM * 2) + c16);
        }
        cp_commit();
    };

    float acc[4][8][4];
    #pragma unroll
    for (int im = 0; im < 4; im++)
        #pragma unroll
        for (int in = 0; in < 8; in++)
            #pragma unroll
            for (int e = 0; e < 4; e++) acc[im][in][e] = 0.f;

    issue(0);
    issue(1);

    const int arow = lane & 15;
    const int acolh = (lane >> 4) * 8;
    const int brow = lane & 7;
    const int bcolh = ((lane >> 3) & 1) * 8;

    #pragma unroll
    for (int s = 0; s < NSTG; ++s) {
        if (s < NSTG - 1) cp_wait<1>(); else cp_wait<0>();
        __syncthreads();
        if (s + 2 < NSTG) issue(s + 2);

        const uint32_t aB = sbase + (s % NBUF) * (2 * BUFSZ);
        const uint32_t bB = aB + BUFSZ;
        #pragma unroll
        for (int kk = 0; kk < 4; kk++) {
            const int k0 = kk * 16;
            uint32_t afr[4][4];
            #pragma unroll
            for (int im = 0; im < 4; im++) {
                uint32_t addr = aB + (warp_m + im * 16 + arow) * SROWB + (k0 + acolh) * 2;
                ldm_x4(afr[im], addr);
            }
            #pragma unroll
            for (int in = 0; in < 8; in++) {
                uint32_t bfr[2];
                uint32_t addr = bB + (warp_n + in * 8 + brow) * SROWB + (k0 + bcolh) * 2;
                ldm_x2(bfr, addr);
                #pragma unroll
                for (int im = 0; im < 4; im++) mma16816(acc[im][in], afr[im], bfr);
            }
        }
    }

    gemm_epilogue(acc, snorm, ncol0, nt, warp_m, warp_n, wid, lane, block_m);
}

// ---------------- merge partials -> index + screen flag list ------------------------
__global__ void merge_kernel(int q) {
    int row = blockIdx.x * blockDim.x + threadIdx.x;
    if (row >= NROWS) return;
    float b1 = -1e30f, b2 = -1e30f;
    int bi = 0;
    const float4* p = &g_part[(size_t)row * NSEG];
    #pragma unroll 8
    for (int s = 0; s < NSEG; s++) {
        float4 v = p[s];
        if (v.x > b1) { b2 = fmaxf(b1, v.y); b1 = v.x; bi = __float_as_int(v.z); }
        else          { b2 = fmaxf(b2, v.x); }
    }
    g_indices[row * NQ + q] = bi;
    if (b1 - b2 < DELTA) {
        int pos = atomicAdd(&g_nflag[q], 1);
        g_flaglist[q * NROWS + pos] = row;
    }
}

// ---------------- rescore: 3-term split GEMM on flagged rows (K=2304) ---------------
__global__ void __launch_bounds__(NTHR, 2)
rescore_gemm_kernel(int q) {
    extern __shared__ char dyn[];
    __shared__ float snorm[GBN];
    __shared__ int   srows[GBM];
    const uint32_t sbase = smem_u32(dyn);

    int nf = g_nflag[q];
    if (nf > MAXRF) nf = MAXRF;
    const int nt = blockIdx.x & (NT2 - 1);
    const int mt = blockIdx.x >> 5;
    if (mt * GBM >= nf) return;

    const int tid = threadIdx.x;
    const int wid = tid >> 5;
    const int lane = tid & 31;
    const int ncol0 = nt * GBN;
    const int warp_m = (wid >> 1) * 64;
    const int warp_n = (wid & 1) * 64;

    snorm[tid] = g_norms[q * NV + ncol0 + tid];
    {
        int slot = mt * GBM + tid;
        srows[tid] = g_flaglist[q * NROWS + min(slot, nf - 1)];
    }
    __syncthreads();

    auto issue = [&](int s) {
        const int b = s % NBUF;
        const int seg3 = s / 12;              // 0: hi*hi  1: hi*lo  2: lo*hi
        const int k0 = (s - seg3 * 12) * BK;
        const __half* Asrc = (seg3 < 2) ? g_Ahi : g_Alo;
        const __half* Bsrc = (seg3 == 1) ? g_Blo : g_Bhi;
        const char* Bb = (const char*)(Bsrc + (size_t)q * NV * DIM)
                         + ((size_t)ncol0 * DIM + k0) * 2;
        const uint32_t dA = sbase + b * (2 * BUFSZ);
        const uint32_t dB = dA + BUFSZ;
        #pragma unroll
        for (int i = 0; i < 8; i++) {
            int ch = tid + i * NTHR;
            int r = ch >> 3, c16 = (ch & 7) * 16;
            const char* Ab = (const char*)(Asrc + (size_t)srows[r] * DIM + k0);
            cp16(dA + r * SROWB + c16, Ab + c16);
        }
        #pragma unroll
        for (int i = 0; i < 8; i++) {
            int ch = tid + i * NTHR;
            int r = ch >> 3, c16 = (ch & 7) * 16;
            cp16(dB + r * SROWB + c16, Bb + (size_t)r * (DIM * 2) + c16);
        }
        cp_commit();
    };

    float acc[4][8][4];
    #pragma unroll
    for (int im = 0; im < 4; im++)
        #pragma unroll
        for (int in = 0; in < 8; in++)
            #pragma unroll
            for (int e = 0; e < 4; e++) acc[im][in][e] = 0.f;

    issue(0);
    issue(1);

    const int arow = lane & 15;
    const int acolh = (lane >> 4) * 8;
    const int brow = lane & 7;
    const int bcolh = ((lane >> 3) & 1) * 8;

    #pragma unroll 1
    for (int s = 0; s < NSTG2; ++s) {
        if (s < NSTG2 - 1) cp_wait<1>(); else cp_wait<0>();
        __syncthreads();
        if (s + 2 < NSTG2) issue(s + 2);

        const uint32_t aB = sbase + (s % NBUF) * (2 * BUFSZ);
        const uint32_t bB = aB + BUFSZ;
        #pragma unroll
        for (int kk = 0; kk < 4; kk++) {
            const int k0 = kk * 16;
            uint32_t afr[4][4];
            #pragma unroll
            for (int im = 0; im < 4; im++) {
                uint32_t addr = aB + (warp_m + im * 16 + arow) * SROWB + (k0 + acolh) * 2;
                ldm_x4(afr[im], addr);
            }
            #pragma unroll
            for (int in = 0; in < 8; in++) {
                uint32_t bfr[2];
                uint32_t addr = bB + (warp_n + in * 8 + brow) * SROWB + (k0 + bcolh) * 2;
                ldm_x2(bfr, addr);
                #pragma unroll
                for (int im = 0; im < 4; im++) mma16816(acc[im][in], afr[im], bfr);
            }
        }
    }

    gemm_epilogue(acc, snorm, ncol0, nt, warp_m, warp_n, wid, lane, mt * GBM);
}

// ---------------- merge rescore partials -> final index (+ fp64 flags) --------------
__global__ void merge2_kernel(int q) {
    int slot = blockIdx.x * blockDim.x + threadIdx.x;
    int nf = g_nflag[q];
    if (nf > MAXRF) nf = MAXRF;
    if (slot >= nf) return;
    float b1 = -1e30f, b2 = -1e30f;
    int bi = 0;
    const float4* p = &g_part[(size_t)slot * NSEG];
    #pragma unroll 8
    for (int s = 0; s < NSEG; s++) {
        float4 v = p[s];
        if (v.x > b1) { b2 = fmaxf(b1, v.y); b1 = v.x; bi = __float_as_int(v.z); }
        else          { b2 = fmaxf(b2, v.x); }
    }
    const int row = g_flaglist[q * NROWS + slot];
    g_indices[row * NQ + q] = bi;
    if (b1 - b2 < TAU2) {
        int pos = atomicAdd(&g_nflag2[q], 1);
        if (pos < MAXF2) g_flag2[q * MAXF2 + pos] = row;
    }
}

// ---------------- fp64 per (row, 256-codeword chunk) --------------------------------
__global__ void __launch_bounds__(256, 1)
refine64_chunk_kernel(const float* __restrict__ cb, int q) {
    __shared__ float  rsm[DIM];
    __shared__ double sred[256];
    __shared__ int    ired[256];

    const int tid = threadIdx.x;
    int nf2 = g_nflag2[q];
    if (nf2 > MAXF2) nf2 = MAXF2;
    const int nwork = nf2 * 16;

    for (int w = blockIdx.x; w < nwork; w += gridDim.x) {
        const int slot = w >> 4;
        const int chunk = w & 15;
        const int row = g_flag2[q * MAXF2 + slot];
        for (int d = tid; d < DIM; d += 256) rsm[d] = g_residual[(size_t)row * DIM + d];
        __syncthreads();

        const int v = chunk * 256 + tid;
        const float4* cv = (const float4*)(cb + (size_t)v * DIM);
        double a0 = 0, a1 = 0, a2 = 0, a3 = 0, a4 = 0, a5 = 0, a6 = 0, a7 = 0;
        #pragma unroll 4
        for (int t = 0; t < DIM / 4; t += 2) {
            float4 c0 = __ldg(cv + t);
            float4 c1 = __ldg(cv + t + 1);
            const float4 r0 = *(const float4*)&rsm[4 * t];
            const float4 r1 = *(const float4*)&rsm[4 * t + 4];
            a0 = fma((double)r0.x, (double)c0.x, a0);
            a1 = fma((double)r0.y, (double)c0.y, a1);
            a2 = fma((double)r0.z, (double)c0.z, a2);
            a3 = fma((double)r0.w, (double)c0.w, a3);
            a4 = fma((double)r1.x, (double)c1.x, a4);
            a5 = fma((double)r1.y, (double)c1.y, a5);
            a6 = fma((double)r1.z, (double)c1.z, a6);
            a7 = fma((double)r1.w, (double)c1.w, a7);
        }
        double dot = ((a0 + a1) + (a2 + a3)) + ((a4 + a5) + (a6 + a7));
        sred[tid] = 2.0 * dot - g_norms64[q * NV + v];
        ired[tid] = v;
        __syncthreads();
        for (int o = 128; o; o >>= 1) {
            if (tid < o) {
                double so = sred[tid + o]; int vo = ired[tid + o];
                if (so > sred[tid] || (so == sred[tid] && vo < ired[tid])) {
                    sred[tid] = so; ired[tid] = vo;
                }
            }
            __syncthreads();
        }
        if (tid == 0) { g_p2s[slot * 16 + chunk] = sred[0]; g_p2i[slot * 16 + chunk] = ired[0]; }
        __syncthreads();
    }
}

// ---------------- reduce fp64 chunk winners -> final index ---------------------------
__global__ void refine64_reduce_kernel(int q) {
    int slot = blockIdx.x * blockDim.x + threadIdx.x;
    int nf2 = g_nflag2[q];
    if (nf2 > MAXF2) nf2 = MAXF2;
    if (slot >= nf2) return;
    double b = -1e300;
    int bi = 0;
    #pragma unroll
    for (int c = 0; c < 16; c++) {
        double s = g_p2s[slot * 16 + c];
        int i = g_p2i[slot * 16 + c];
        if (s > b || (s == b && i < bi)) { b = s; bi = i; }
    }
    const int row = g_flag2[q * MAXF2 + slot];
    g_indices[row * NQ + q] = bi;
}

// ---------------- gather + residual update (+ fp16 hi/lo unless last level) ---------
__global__ void update_kernel(const float* __restrict__ cb, int q, int last) {
    int gid = blockIdx.x * blockDim.x + threadIdx.x;
    const int PR = DIM / 4;
    int row = gid / PR;
    if (row >= NROWS) return;
    int c = (gid - row * PR) << 2;
    int idx = __ldg(&g_indices[row * NQ + q]);
    const float4 cw = *(const float4*)(cb + (size_t)idx * DIM + c);
    size_t off = (size_t)row * DIM + c;
    float4 r = *(float4*)(g_residual + off);
    r.x -= cw.x; r.y -= cw.y; r.z -= cw.z; r.w -= cw.w;
    *(float4*)(g_residual + off) = r;
    if (!last) store_hilo4(g_Ahi + (size_t)row * DIM, g_Alo + (size_t)row * DIM, c, r);
}

// ---------------- out = x + (quantized - x), quantized = x - residual ---------------
__global__ void finalize_kernel(const float* __restrict__ x, float* __restrict__ out) {
    size_t i = (size_t)blockIdx.x * blockDim.x + threadIdx.x;
    if (i >= (size_t)NROWS * DIM / 4) return;
    float4 xv = ((const float4*)x)[i];
    float4 rv = ((const float4*)g_residual)[i];
    float4 qv;
    qv.x = xv.x - rv.x; qv.y = xv.y - rv.y; qv.z = xv.z - rv.z; qv.w = xv.w - rv.w;
    float4 o;
    o.x = xv.x + (qv.x - xv.x);
    o.y = xv.y + (qv.y - xv.y);
    o.z = xv.z + (qv.z - xv.z);
    o.w = xv.w + (qv.w - xv.w);
    ((float4*)out)[i] = o;
}

__global__ void idxout_kernel(float* __restrict__ out) {
    int i = blockIdx.x * blockDim.x + threadIdx.x;
    if (i < NROWS * NQ) out[i] = (float)g_indices[i];
}

extern "C" void kernel_launch(void* const* d_in, const int* in_sizes, int n_in,
                              void* d_out, int out_size) {
    const float* x  = (const float*)d_in[0];
    const float* cb = (const float*)d_in[1];
    float* out = (float*)d_out;

    cudaFuncSetAttribute(score_gemm_kernel,
                         cudaFuncAttributeMaxDynamicSharedMemorySize, SMEM_DYN);
    cudaFuncSetAttribute(rescore_gemm_kernel,
                         cudaFuncAttributeMaxDynamicSharedMemorySize, SMEM_DYN);

    norms_kernel<<<(NQ * NV) / 8, 256>>>(cb);
    init_kernel<<<(NROWS * DIM / 4 + 255) / 256, 256>>>(x);
    convB_kernel<<<(NQ * NV * (DIM / 4) + 255) / 256, 256>>>(cb);

    for (int q = 0; q < NQ; q++) {
        const float* cbq = cb + (size_t)q * NV * DIM;
        score_gemm_kernel<<<MT2 * NT2, NTHR, SMEM_DYN>>>(q);
        merge_kernel<<<(NROWS + 255) / 256, 256>>>(q);
        rescore_gemm_kernel<<<(MAXRF / GBM) * NT2, NTHR, SMEM_DYN>>>(q);
        merge2_kernel<<<(MAXRF + 255) / 256, 256>>>(q);
        refine64_chunk_kernel<<<592, 256>>>(cbq, q);
        refine64_reduce_kernel<<<(MAXF2 + 255) / 256, 256>>>(q);
        update_kernel<<<(NROWS * (DIM / 4) + 255) / 256, 256>>>(cbq, q, q == NQ - 1);
    }

    finalize_kernel<<<(NROWS * DIM / 4 + 255) / 256, 256>>>(x, out);

    if (out_size >= NROWS * DIM + NROWS * NQ) {
        idxout_kernel<<<(NROWS * NQ + 255) / 256, 256>>>(out + (size_t)NROWS * DIM);
    }
}

// round 13
// speedup vs baseline: 10.8666x; 1.0058x over previous
#include <cuda_runtime.h>
#include <cuda_fp16.h>
#include <cstdint>

#define NROWS 32768
#define DIM   768
#define NQ    4
#define NV    4096
#define DELTA 0.20f      // screen flag threshold (~6.5 sigma of fp16-GEMM pairwise err)
#define TAU2  2e-3f      // rescore -> fp64 threshold (~20 sigma of 3-term GEMM err)
#define MAXF2 4096       // fp64 slot cap
#define MAXRF 4096       // rescore row capacity

#define GBM 128
#define GBN 128
#define KTOT 768
#define BK   64
#define NSTG (KTOT / BK)   // 12 (screen)
#define NSTG2 36           // rescore: 3*768/64
#define NBUF 3
#define NT2  (NV / GBN)    // 32
#define MT2  (NROWS / GBM) // 256
#define SROW  72
#define SROWB 144
#define BUFSZ (128 * SROWB)
#define SMEM_DYN (NBUF * 2 * BUFSZ)
#define NSEG 64            // NT2 * 2 n-warp segments of 64 cols
#define NTHR 128           // 4 warps: 2m x 2n, warp tile 64x64

// ---------------- scratch ---------------------------------------------------------
__device__ float  g_residual[(size_t)NROWS * DIM];
__device__ float  g_norms[NQ * NV];
__device__ double g_norms64[NQ * NV];
__device__ int    g_indices[NROWS * NQ];
__device__ int    g_nflag[NQ];
__device__ int    g_flaglist[NQ * NROWS];
__device__ int    g_nflag2[NQ];
__device__ int    g_flag2[NQ * MAXF2];
__device__ double g_p2s[MAXF2 * 16];
__device__ int    g_p2i[MAXF2 * 16];
__device__ __align__(256) __half g_Ahi[(size_t)NROWS * DIM];
__device__ __align__(256) __half g_Alo[(size_t)NROWS * DIM];
__device__ __align__(256) __half g_Bhi[(size_t)NQ * NV * DIM];
__device__ __align__(256) __half g_Blo[(size_t)NQ * NV * DIM];
__device__ float4 g_part[(size_t)NROWS * NSEG];   // screen partials; reused by rescore

// ---------------- PTX helpers ------------------------------------------------------
__device__ __forceinline__ uint32_t smem_u32(const void* p) {
    uint32_t a;
    asm("{ .reg .u64 t; cvta.to.shared.u64 t, %1; cvt.u32.u64 %0, t; }" : "=r"(a) : "l"(p));
    return a;
}
__device__ __forceinline__ void cp16(uint32_t s, const void* g) {
    asm volatile("cp.async.cg.shared.global [%0], [%1], 16;" :: "r"(s), "l"(g));
}
__device__ __forceinline__ void cp_commit() { asm volatile("cp.async.commit_group;"); }
template <int N>
__device__ __forceinline__ void cp_wait() { asm volatile("cp.async.wait_group %0;" :: "n"(N) : "memory"); }

__device__ __forceinline__ void ldm_x4(uint32_t* r, uint32_t a) {
    asm volatile("ldmatrix.sync.aligned.m8n8.x4.shared.b16 {%0,%1,%2,%3}, [%4];"
                 : "=r"(r[0]), "=r"(r[1]), "=r"(r[2]), "=r"(r[3]) : "r"(a));
}
__device__ __forceinline__ void ldm_x2(uint32_t* r, uint32_t a) {
    asm volatile("ldmatrix.sync.aligned.m8n8.x2.shared.b16 {%0,%1}, [%2];"
                 : "=r"(r[0]), "=r"(r[1]) : "r"(a));
}
__device__ __forceinline__ void mma16816(float* d, const uint32_t* a, const uint32_t* b) {
    asm volatile("mma.sync.aligned.m16n8k16.row.col.f32.f16.f16.f32 "
                 "{%0,%1,%2,%3}, {%4,%5,%6,%7}, {%8,%9}, {%0,%1,%2,%3};"
                 : "+f"(d[0]), "+f"(d[1]), "+f"(d[2]), "+f"(d[3])
                 : "r"(a[0]), "r"(a[1]), "r"(a[2]), "r"(a[3]), "r"(b[0]), "r"(b[1]));
}

__device__ __forceinline__ void store_hilo4(__half* hb, __half* lb, int c, float4 r) {
    __half h0 = __float2half_rn(r.x), h1 = __float2half_rn(r.y);
    __half h2 = __float2half_rn(r.z), h3 = __float2half_rn(r.w);
    *(__half2*)(hb + c)     = __halves2half2(h0, h1);
    *(__half2*)(hb + c + 2) = __halves2half2(h2, h3);
    *(__half2*)(lb + c)     = __halves2half2(__float2half_rn(r.x - __half2float(h0)),
                                             __float2half_rn(r.y - __half2float(h1)));
    *(__half2*)(lb + c + 2) = __halves2half2(__float2half_rn(r.z - __half2float(h2)),
                                             __float2half_rn(r.w - __half2float(h3)));
}

// ---------------- ||c||^2 per codeword (fp64 + fp32 copy) --------------------------
__global__ void norms_kernel(const float* __restrict__ cb) {
    int w = (blockIdx.x * blockDim.x + threadIdx.x) >> 5;
    int lane = threadIdx.x & 31;
    if (w >= NQ * NV) return;
    const float* c = cb + (size_t)w * DIM;
    double s = 0.0;
    #pragma unroll 4
    for (int d = lane; d < DIM; d += 32) {
        double v = (double)__ldg(c + d);
        s = fma(v, v, s);
    }
    #pragma unroll
    for (int o = 16; o; o >>= 1) s += __shfl_xor_sync(0xffffffffu, s, o);
    if (lane == 0) { g_norms64[w] = s; g_norms[w] = (float)s; }
}

// ---------------- residual = x (+ fp16 hi/lo), flags = 0 ----------------------------
__global__ void init_kernel(const float* __restrict__ x) {
    size_t i = (size_t)blockIdx.x * blockDim.x + threadIdx.x;
    if (i < NQ) { g_nflag[i] = 0; g_nflag2[i] = 0; }
    if (i >= (size_t)NROWS * DIM / 4) return;
    float4 v = ((const float4*)x)[i];
    ((float4*)g_residual)[i] = v;
    int row = (int)(i / (DIM / 4));
    int c = (int)(i - (size_t)row * (DIM / 4)) * 4;
    store_hilo4(g_Ahi + (size_t)row * DIM, g_Alo + (size_t)row * DIM, c, v);
}

// ---------------- codebooks -> fp16 hi/lo (once) ------------------------------------
__global__ void convB_kernel(const float* __restrict__ cb) {
    int i = blockIdx.x * blockDim.x + threadIdx.x;
    if (i >= NQ * NV * (DIM / 4)) return;
    float4 v = *(const float4*)(cb + (size_t)i * 4);
    store_hilo4(g_Bhi, g_Blo, i * 4, v);
}

// ======== shared tile-compute pieces for 4-warp 128x128 block, warp tile 64x64 ======

// batched fragment-load + mma for one BK=64 stage (2 pairs of 2 k-slices)
__device__ __forceinline__ void stage_compute(
    float acc[4][8][4], uint32_t aB, uint32_t bB,
    int warp_m, int warp_n, int arow, int acolh, int brow, int bcolh) {
    #pragma unroll
    for (int kp = 0; kp < 2; kp++) {
        uint32_t afr[2][4][4];
        uint32_t bfr[2][8][2];
        #pragma unroll
        for (int h = 0; h < 2; h++) {
            const int k0 = (kp * 2 + h) * 16;
            #pragma unroll
            for (int im = 0; im < 4; im++)
                ldm_x4(afr[h][im], aB + (warp_m + im * 16 + arow) * SROWB + (k0 + acolh) * 2);
            #pragma unroll
            for (int in = 0; in < 8; in++)
                ldm_x2(bfr[h][in], bB + (warp_n + in * 8 + brow) * SROWB + (k0 + bcolh) * 2);
        }
        #pragma unroll
        for (int h = 0; h < 2; h++)
            #pragma unroll
            for (int in = 0; in < 8; in++)
                #pragma unroll
                for (int im = 0; im < 4; im++)
                    mma16816(acc[im][in], afr[h][im], bfr[h][in]);
    }
}

// epilogue writes per-slot top-2 into g_part[slotbase + ...]
__device__ __forceinline__ void gemm_epilogue(
    float acc[4][8][4], const float* snorm, int ncol0, int nt,
    int warp_m, int warp_n, int wid, int lane, int slot_base) {
    const int seg = nt * 2 + (wid & 1);
    #pragma unroll
    for (int im = 0; im < 4; im++) {
        float t1a = -1e30f, t2a = -1e30f, t1b = -1e30f, t2b = -1e30f;
        int i1a = 0, i1b = 0;
        #pragma unroll
        for (int in = 0; in < 8; in++) {
            int c = warp_n + in * 8 + (lane & 3) * 2;
            float n0 = snorm[c], n1 = snorm[c + 1];
            float sa0 = fmaf(2.f, acc[im][in][0], -n0);
            float sa1 = fmaf(2.f, acc[im][in][1], -n1);
            float sb0 = fmaf(2.f, acc[im][in][2], -n0);
            float sb1 = fmaf(2.f, acc[im][in][3], -n1);
            int gc = ncol0 + c;
            if (sa0 > t1a) { t2a = t1a; t1a = sa0; i1a = gc; } else if (sa0 > t2a) t2a = sa0;
            if (sa1 > t1a) { t2a = t1a; t1a = sa1; i1a = gc + 1; } else if (sa1 > t2a) t2a = sa1;
            if (sb0 > t1b) { t2b = t1b; t1b = sb0; i1b = gc; } else if (sb0 > t2b) t2b = sb0;
            if (sb1 > t1b) { t2b = t1b; t1b = sb1; i1b = gc + 1; } else if (sb1 > t2b) t2b = sb1;
        }
        #pragma unroll
        for (int o = 1; o < 4; o <<= 1) {
            float u1 = __shfl_xor_sync(0xffffffffu, t1a, o);
            float u2 = __shfl_xor_sync(0xffffffffu, t2a, o);
            int   ui = __shfl_xor_sync(0xffffffffu, i1a, o);
            if (u1 > t1a || (u1 == t1a && ui < i1a)) { t2a = fmaxf(t1a, u2); t1a = u1; i1a = ui; }
            else t2a = fmaxf(t2a, u1);
            float v1 = __shfl_xor_sync(0xffffffffu, t1b, o);
            float v2 = __shfl_xor_sync(0xffffffffu, t2b, o);
            int   vi = __shfl_xor_sync(0xffffffffu, i1b, o);
            if (v1 > t1b || (v1 == t1b && vi < i1b)) { t2b = fmaxf(t1b, v2); t1b = v1; i1b = vi; }
            else t2b = fmaxf(t2b, v1);
        }
        if ((lane & 3) == 0) {
            int rA = slot_base + warp_m + im * 16 + (lane >> 2);
            g_part[(size_t)rA * NSEG + seg] = make_float4(t1a, t2a, __int_as_float(i1a), 0.f);
            g_part[(size_t)(rA + 8) * NSEG + seg] = make_float4(t1b, t2b, __int_as_float(i1b), 0.f);
        }
    }
}

// ---------------- mma.sync screen GEMM (K=768, hi only) ------------------------------
__global__ void __launch_bounds__(NTHR, 2)
score_gemm_kernel(int q) {
    extern __shared__ char dyn[];
    __shared__ float snorm[GBN];
    const uint32_t sbase = smem_u32(dyn);

    const int tid = threadIdx.x;
    const int wid = tid >> 5;
    const int lane = tid & 31;
    const int nt = blockIdx.x & (NT2 - 1);
    const int mt = blockIdx.x >> 5;
    const int block_m = mt * GBM;
    const int ncol0 = nt * GBN;
    const int warp_m = (wid >> 1) * 64;
    const int warp_n = (wid & 1) * 64;

    snorm[tid] = g_norms[q * NV + ncol0 + tid];

    const char* Abase = (const char*)g_Ahi + (size_t)block_m * DIM * 2;
    const char* Bbase = (const char*)(g_Bhi + (size_t)q * NV * DIM)
                        + (size_t)ncol0 * DIM * 2;

    auto issue = [&](int s) {
        const int b = s % NBUF;
        const int k0 = s * BK;
        const uint32_t dA = sbase + b * (2 * BUFSZ);
        const uint32_t dB = dA + BUFSZ;
        const char* Ab = Abase + (size_t)k0 * 2;
        const char* Bb = Bbase + (size_t)k0 * 2;
        #pragma unroll
        for (int i = 0; i < 8; i++) {
            int ch = tid + i * NTHR;
            int r = ch >> 3, c16 = (ch & 7) * 16;
            cp16(dA + r * SROWB + c16, Ab + (size_t)r * (DIM * 2) + c16);
        }
        #pragma unroll
        for (int i = 0; i < 8; i++) {
            int ch = tid + i * NTHR;
            int r = ch >> 3, c16 = (ch & 7) * 16;
            cp16(dB + r * SROWB + c16, Bb + (size_t)r * (DIM * 2) + c16);
        }
        cp_commit();
    };

    float acc[4][8][4];
    #pragma unroll
    for (int im = 0; im < 4; im++)
        #pragma unroll
        for (int in = 0; in < 8; in++)
            #pragma unroll
            for (int e = 0; e < 4; e++) acc[im][in][e] = 0.f;

    issue(0);
    issue(1);

    const int arow = lane & 15;
    const int acolh = (lane >> 4) * 8;
    const int brow = lane & 7;
    const int bcolh = ((lane >> 3) & 1) * 8;

    #pragma unroll
    for (int s = 0; s < NSTG; ++s) {
        if (s < NSTG - 1) cp_wait<1>(); else cp_wait<0>();
        __syncthreads();
        if (s + 2 < NSTG) issue(s + 2);
        const uint32_t aB = sbase + (s % NBUF) * (2 * BUFSZ);
        stage_compute(acc, aB, aB + BUFSZ, warp_m, warp_n, arow, acolh, brow, bcolh);
    }

    gemm_epilogue(acc, snorm, ncol0, nt, warp_m, warp_n, wid, lane, block_m);
}

// ---------------- merge partials -> index + screen flag list ------------------------
__global__ void merge_kernel(int q) {
    int row = blockIdx.x * blockDim.x + threadIdx.x;
    if (row >= NROWS) return;
    float b1 = -1e30f, b2 = -1e30f;
    int bi = 0;
    const float4* p = &g_part[(size_t)row * NSEG];
    #pragma unroll 8
    for (int s = 0; s < NSEG; s++) {
        float4 v = p[s];
        if (v.x > b1) { b2 = fmaxf(b1, v.y); b1 = v.x; bi = __float_as_int(v.z); }
        else          { b2 = fmaxf(b2, v.x); }
    }
    g_indices[row * NQ + q] = bi;
    if (b1 - b2 < DELTA) {
        int pos = atomicAdd(&g_nflag[q], 1);
        g_flaglist[q * NROWS + pos] = row;
    }
}

// ---------------- rescore: 3-term split GEMM on flagged rows (K=2304) ---------------
__global__ void __launch_bounds__(NTHR, 2)
rescore_gemm_kernel(int q) {
    extern __shared__ char dyn[];
    __shared__ float snorm[GBN];
    __shared__ int   srows[GBM];
    const uint32_t sbase = smem_u32(dyn);

    int nf = g_nflag[q];
    if (nf > MAXRF) nf = MAXRF;
    const int nt = blockIdx.x & (NT2 - 1);
    const int mt = blockIdx.x >> 5;
    if (mt * GBM >= nf) return;

    const int tid = threadIdx.x;
    const int wid = tid >> 5;
    const int lane = tid & 31;
    const int ncol0 = nt * GBN;
    const int warp_m = (wid >> 1) * 64;
    const int warp_n = (wid & 1) * 64;

    snorm[tid] = g_norms[q * NV + ncol0 + tid];
    {
        int slot = mt * GBM + tid;
        srows[tid] = g_flaglist[q * NROWS + min(slot, nf - 1)];
    }
    __syncthreads();

    auto issue = [&](int s) {
        const int b = s % NBUF;
        const int seg3 = s / 12;              // 0: hi*hi  1: hi*lo  2: lo*hi
        const int k0 = (s - seg3 * 12) * BK;
        const __half* Asrc = (seg3 < 2) ? g_Ahi : g_Alo;
        const __half* Bsrc = (seg3 == 1) ? g_Blo : g_Bhi;
        const char* Bb = (const char*)(Bsrc + (size_t)q * NV * DIM)
                         + ((size_t)ncol0 * DIM + k0) * 2;
        const uint32_t dA = sbase + b * (2 * BUFSZ);
        const uint32_t dB = dA + BUFSZ;
        #pragma unroll
        for (int i = 0; i < 8; i++) {
            int ch = tid + i * NTHR;
            int r = ch >> 3, c16 = (ch & 7) * 16;
            const char* Ab = (const char*)(Asrc + (size_t)srows[r] * DIM + k0);
            cp16(dA + r * SROWB + c16, Ab + c16);
        }
        #pragma unroll
        for (int i = 0; i < 8; i++) {
            int ch = tid + i * NTHR;
            int r = ch >> 3, c16 = (ch & 7) * 16;
            cp16(dB + r * SROWB + c16, Bb + (size_t)r * (DIM * 2) + c16);
        }
        cp_commit();
    };

    float acc[4][8][4];
    #pragma unroll
    for (int im = 0; im < 4; im++)
        #pragma unroll
        for (int in = 0; in < 8; in++)
            #pragma unroll
            for (int e = 0; e < 4; e++) acc[im][in][e] = 0.f;

    issue(0);
    issue(1);

    const int arow = lane & 15;
    const int acolh = (lane >> 4) * 8;
    const int brow = lane & 7;
    const int bcolh = ((lane >> 3) & 1) * 8;

    #pragma unroll 1
    for (int s = 0; s < NSTG2; ++s) {
        if (s < NSTG2 - 1) cp_wait<1>(); else cp_wait<0>();
        __syncthreads();
        if (s + 2 < NSTG2) issue(s + 2);
        const uint32_t aB = sbase + (s % NBUF) * (2 * BUFSZ);
        stage_compute(acc, aB, aB + BUFSZ, warp_m, warp_n, arow, acolh, brow, bcolh);
    }

    gemm_epilogue(acc, snorm, ncol0, nt, warp_m, warp_n, wid, lane, mt * GBM);
}

// ---------------- merge rescore partials -> final index (+ fp64 flags) --------------
__global__ void merge2_kernel(int q) {
    int slot = blockIdx.x * blockDim.x + threadIdx.x;
    int nf = g_nflag[q];
    if (nf > MAXRF) nf = MAXRF;
    if (slot >= nf) return;
    float b1 = -1e30f, b2 = -1e30f;
    int bi = 0;
    const float4* p = &g_part[(size_t)slot * NSEG];
    #pragma unroll 8
    for (int s = 0; s < NSEG; s++) {
        float4 v = p[s];
        if (v.x > b1) { b2 = fmaxf(b1, v.y); b1 = v.x; bi = __float_as_int(v.z); }
        else          { b2 = fmaxf(b2, v.x); }
    }
    const int row = g_flaglist[q * NROWS + slot];
    g_indices[row * NQ + q] = bi;
    if (b1 - b2 < TAU2) {
        int pos = atomicAdd(&g_nflag2[q], 1);
        if (pos < MAXF2) g_flag2[q * MAXF2 + pos] = row;
    }
}

// ---------------- fp64 per (row, 256-codeword chunk) --------------------------------
__global__ void __launch_bounds__(256, 1)
refine64_chunk_kernel(const float* __restrict__ cb, int q) {
    __shared__ float  rsm[DIM];
    __shared__ double sred[256];
    __shared__ int    ired[256];

    const int tid = threadIdx.x;
    int nf2 = g_nflag2[q];
    if (nf2 > MAXF2) nf2 = MAXF2;
    const int nwork = nf2 * 16;

    for (int w = blockIdx.x; w < nwork; w += gridDim.x) {
        const int slot = w >> 4;
        const int chunk = w & 15;
        const int row = g_flag2[q * MAXF2 + slot];
        for (int d = tid; d < DIM; d += 256) rsm[d] = g_residual[(size_t)row * DIM + d];
        __syncthreads();

        const int v = chunk * 256 + tid;
        const float4* cv = (const float4*)(cb + (size_t)v * DIM);
        double a0 = 0, a1 = 0, a2 = 0, a3 = 0, a4 = 0, a5 = 0, a6 = 0, a7 = 0;
        #pragma unroll 4
        for (int t = 0; t < DIM / 4; t += 2) {
            float4 c0 = __ldg(cv + t);
            float4 c1 = __ldg(cv + t + 1);
            const float4 r0 = *(const float4*)&rsm[4 * t];
            const float4 r1 = *(const float4*)&rsm[4 * t + 4];
            a0 = fma((double)r0.x, (double)c0.x, a0);
            a1 = fma((double)r0.y, (double)c0.y, a1);
            a2 = fma((double)r0.z, (double)c0.z, a2);
            a3 = fma((double)r0.w, (double)c0.w, a3);
            a4 = fma((double)r1.x, (double)c1.x, a4);
            a5 = fma((double)r1.y, (double)c1.y, a5);
            a6 = fma((double)r1.z, (double)c1.z, a6);
            a7 = fma((double)r1.w, (double)c1.w, a7);
        }
        double dot = ((a0 + a1) + (a2 + a3)) + ((a4 + a5) + (a6 + a7));
        sred[tid] = 2.0 * dot - g_norms64[q * NV + v];
        ired[tid] = v;
        __syncthreads();
        for (int o = 128; o; o >>= 1) {
            if (tid < o) {
                double so = sred[tid + o]; int vo = ired[tid + o];
                if (so > sred[tid] || (so == sred[tid] && vo < ired[tid])) {
                    sred[tid] = so; ired[tid] = vo;
                }
            }
            __syncthreads();
        }
        if (tid == 0) { g_p2s[slot * 16 + chunk] = sred[0]; g_p2i[slot * 16 + chunk] = ired[0]; }
        __syncthreads();
    }
}

// ---------------- reduce fp64 chunk winners -> final index ---------------------------
__global__ void refine64_reduce_kernel(int q) {
    int slot = blockIdx.x * blockDim.x + threadIdx.x;
    int nf2 = g_nflag2[q];
    if (nf2 > MAXF2) nf2 = MAXF2;
    if (slot >= nf2) return;
    double b = -1e300;
    int bi = 0;
    #pragma unroll
    for (int c = 0; c < 16; c++) {
        double s = g_p2s[slot * 16 + c];
        int i = g_p2i[slot * 16 + c];
        if (s > b || (s == b && i < bi)) { b = s; bi = i; }
    }
    const int row = g_flag2[q * MAXF2 + slot];
    g_indices[row * NQ + q] = bi;
}

// ---------------- gather + residual update; last level writes output directly --------
__global__ void update_kernel(const float* __restrict__ cb, const float* __restrict__ x,
                              float* __restrict__ out, int q, int last) {
    int gid = blockIdx.x * blockDim.x + threadIdx.x;
    const int PR = DIM / 4;
    int row = gid / PR;
    if (row >= NROWS) return;
    int c = (gid - row * PR) << 2;
    int idx = __ldg(&g_indices[row * NQ + q]);
    const float4 cw = *(const float4*)(cb + (size_t)idx * DIM + c);
    size_t off = (size_t)row * DIM + c;
    float4 r = *(float4*)(g_residual + off);
    r.x -= cw.x; r.y -= cw.y; r.z -= cw.z; r.w -= cw.w;
    if (!last) {
        *(float4*)(g_residual + off) = r;
        store_hilo4(g_Ahi + (size_t)row * DIM, g_Alo + (size_t)row * DIM, c, r);
    } else {
        // out = x + (quantized - x), quantized = x - r_final
        float4 xv = *(const float4*)(x + off);
        float4 qv;
        qv.x = xv.x - r.x; qv.y = xv.y - r.y; qv.z = xv.z - r.z; qv.w = xv.w - r.w;
        float4 o;
        o.x = xv.x + (qv.x - xv.x);
        o.y = xv.y + (qv.y - xv.y);
        o.z = xv.z + (qv.z - xv.z);
        o.w = xv.w + (qv.w - xv.w);
        *(float4*)(out + off) = o;
    }
}

__global__ void idxout_kernel(float* __restrict__ out) {
    int i = blockIdx.x * blockDim.x + threadIdx.x;
    if (i < NROWS * NQ) out[i] = (float)g_indices[i];
}

extern "C" void kernel_launch(void* const* d_in, const int* in_sizes, int n_in,
                              void* d_out, int out_size) {
    const float* x  = (const float*)d_in[0];
    const float* cb = (const float*)d_in[1];
    float* out = (float*)d_out;

    cudaFuncSetAttribute(score_gemm_kernel,
                         cudaFuncAttributeMaxDynamicSharedMemorySize, SMEM_DYN);
    cudaFuncSetAttribute(rescore_gemm_kernel,
                         cudaFuncAttributeMaxDynamicSharedMemorySize, SMEM_DYN);

    norms_kernel<<<(NQ * NV) / 8, 256>>>(cb);
    init_kernel<<<(NROWS * DIM / 4 + 255) / 256, 256>>>(x);
    convB_kernel<<<(NQ * NV * (DIM / 4) + 255) / 256, 256>>>(cb);

    for (int q = 0; q < NQ; q++) {
        const float* cbq = cb + (size_t)q * NV * DIM;
        score_gemm_kernel<<<MT2 * NT2, NTHR, SMEM_DYN>>>(q);
        merge_kernel<<<(NROWS + 255) / 256, 256>>>(q);
        rescore_gemm_kernel<<<(MAXRF / GBM) * NT2, NTHR, SMEM_DYN>>>(q);
        merge2_kernel<<<(MAXRF + 255) / 256, 256>>>(q);
        refine64_chunk_kernel<<<592, 256>>>(cbq, q);
        refine64_reduce_kernel<<<(MAXF2 + 255) / 256, 256>>>(q);
        update_kernel<<<(NROWS * (DIM / 4) + 255) / 256, 256>>>(cbq, x, out, q, q == NQ - 1);
    }

    if (out_size >= NROWS * DIM + NROWS * NQ) {
        idxout_kernel<<<(NROWS * NQ + 255) / 256, 256>>>(out + (size_t)NROWS * DIM);
    }
}